// round 15
// baseline (speedup 1.0000x reference)
#include <cuda_runtime.h>
#include <cuda_bf16.h>
#include <cstdint>
#include <cstddef>
#include <math.h>

constexpr int NB=8, NC=512, NSQ=2048, NSQ2=1024, NSQ4=512, NSKV=512, NH=4, NHD=128;
constexpr float F_PS = 0.31622776601683794f;
constexpr float F_S2 = 1.0f / 128.0f;

__device__ float g_tmp[NB * NC * NSQ];
__device__ float g_x0 [NB * NC * NSQ2];
__device__ float g_x1 [NB * NC * NSQ4];
__device__ float g_qx [NB * NSQ2 * NC];
__device__ float g_q  [NB * NSQ2 * NC];
__device__ float g_k  [NB * NSKV * NC];
__device__ float g_v  [NB * NSKV * NC];
__device__ float g_x2 [NB * NH * NSQ2];
__device__ float g_y2 [NB * NH * NSKV];
__device__ float g_a0 [NB * NH * NSQ2 * NSKV];
__device__ float g_a1 [NB * NH * NSQ2 * NSKV];
__device__ float g_y  [NB * NSQ2 * NC];
__device__ __nv_bfloat16 g_inqh [NB * NSQ * NC];
__device__ __nv_bfloat16 g_inql [NB * NSQ * NC];
__device__ __nv_bfloat16 g_inkvh[NB * NSKV * NC];
__device__ __nv_bfloat16 g_inkvl[NB * NSKV * NC];
__device__ __nv_bfloat16 g_whi1[NC * NC * 3];
__device__ __nv_bfloat16 g_wlo1[NC * NC * 3];
__device__ __nv_bfloat16 g_whi2[NC * NC * 3];
__device__ __nv_bfloat16 g_wlo2[NC * NC * 3];
__device__ __nv_bfloat16 g_pwhi[4 * NC * NC];
__device__ __nv_bfloat16 g_pwlo[4 * NC * NC];
constexpr int SCW_N = 4 * 5 * 4 * 2 * 112;
__device__ uint32_t g_scw[SCW_N];

__device__ __forceinline__ uint32_t smem_u32(const void* p) {
    uint32_t a;
    asm("{ .reg .u64 t; cvta.to.shared.u64 t, %1; cvt.u32.u64 %0, t; }" : "=r"(a) : "l"(p));
    return a;
}
__device__ __forceinline__ void ldsm_x4(uint32_t* r, uint32_t addr) {
    asm volatile("ldmatrix.sync.aligned.m8n8.x4.shared.b16 {%0,%1,%2,%3}, [%4];"
        : "=r"(r[0]), "=r"(r[1]), "=r"(r[2]), "=r"(r[3]) : "r"(addr));
}
__device__ __forceinline__ void ldsm_x2(uint32_t* r, uint32_t addr) {
    asm volatile("ldmatrix.sync.aligned.m8n8.x2.shared.b16 {%0,%1}, [%2];"
        : "=r"(r[0]), "=r"(r[1]) : "r"(addr));
}
__device__ __forceinline__ void mma_bf16(float* c, const uint32_t* a, const uint32_t* b) {
    asm volatile("mma.sync.aligned.m16n8k16.row.col.f32.bf16.bf16.f32 "
        "{%0,%1,%2,%3}, {%4,%5,%6,%7}, {%8,%9}, {%0,%1,%2,%3};"
        : "+f"(c[0]), "+f"(c[1]), "+f"(c[2]), "+f"(c[3])
        : "r"(a[0]), "r"(a[1]), "r"(a[2]), "r"(a[3]), "r"(b[0]), "r"(b[1]));
}
__device__ __forceinline__ uint32_t packhl(__nv_bfloat16 a, __nv_bfloat16 b) {
    uint16_t ua = *reinterpret_cast<uint16_t*>(&a);
    uint16_t ub = *reinterpret_cast<uint16_t*>(&b);
    return (uint32_t)ua | ((uint32_t)ub << 16);
}
__device__ __forceinline__ void split8(const float* f, uint4& hi, uint4& lo) {
    __nv_bfloat16 h[8], l[8];
    #pragma unroll
    for (int i = 0; i < 8; i++) {
        h[i] = __float2bfloat16(f[i]);
        l[i] = __float2bfloat16(f[i] - __bfloat162float(h[i]));
    }
    hi = make_uint4(packhl(h[0],h[1]), packhl(h[2],h[3]), packhl(h[4],h[5]), packhl(h[6],h[7]));
    lo = make_uint4(packhl(l[0],l[1]), packhl(l[2],l[3]), packhl(l[4],l[5]), packhl(l[6],l[7]));
}
__device__ __forceinline__ void cp16(uint32_t d, const void* s, bool ok) {
    int sz = ok ? 16 : 0;
    asm volatile("cp.async.cg.shared.global [%0], [%1], 16, %2;" :: "r"(d), "l"(s), "r"(sz) : "memory");
}
#define CP_COMMIT() asm volatile("cp.async.commit_group;" ::: "memory")
#define CP_WAIT0()  asm volatile("cp.async.wait_group 0;" ::: "memory")

constexpr int SM_A_HI = 0, SM_A_LO = 9216, SM_B_HI = 18432, SM_B_LO = 36864, SM_TOT = 55296;
// conv 128x128 tile layout (144B row stride)
constexpr int C1_A_HI = 0, C1_A_LO = 18432, C1_B_HI = 36864, C1_B_LO = 55296, C1_TOT = 73728;

__device__ __forceinline__ void mma_chunk(uint32_t aHiB, uint32_t aLoB,
                                          uint32_t bHiB, uint32_t bLoB,
                                          float acc[2][4][4]) {
    #pragma unroll
    for (int k16 = 0; k16 < 4; k16++) {
        uint32_t ah[2][4], al[2][4], bh[4][2], bl[4][2];
        #pragma unroll
        for (int i = 0; i < 2; i++) {
            ldsm_x4(ah[i], aHiB + i * 2304 + k16 * 32);
            ldsm_x4(al[i], aLoB + i * 2304 + k16 * 32);
        }
        #pragma unroll
        for (int j = 0; j < 4; j++) {
            ldsm_x2(bh[j], bHiB + j * 1152 + k16 * 32);
            ldsm_x2(bl[j], bLoB + j * 1152 + k16 * 32);
        }
        #pragma unroll
        for (int i = 0; i < 2; i++)
            #pragma unroll
            for (int j = 0; j < 4; j++) {
                mma_bf16(acc[i][j], ah[i], bh[j]);
                mma_bf16(acc[i][j], al[i], bh[j]);
                mma_bf16(acc[i][j], ah[i], bl[j]);
            }
    }
}

// 128x128 variant: warp tile 32m x 64n, acc[2][8][4]; B handled in two 4-j halves
__device__ __forceinline__ void mma_chunk128(uint32_t aHiB, uint32_t aLoB,
                                             uint32_t bHiB, uint32_t bLoB,
                                             float acc[2][8][4]) {
    #pragma unroll
    for (int k16 = 0; k16 < 4; k16++) {
        uint32_t ah[2][4], al[2][4];
        #pragma unroll
        for (int i = 0; i < 2; i++) {
            ldsm_x4(ah[i], aHiB + i * 2304 + k16 * 32);
            ldsm_x4(al[i], aLoB + i * 2304 + k16 * 32);
        }
        #pragma unroll
        for (int jh = 0; jh < 2; jh++) {
            uint32_t bh[4][2], bl[4][2];
            #pragma unroll
            for (int j = 0; j < 4; j++) {
                ldsm_x2(bh[j], bHiB + (jh * 4 + j) * 1152 + k16 * 32);
                ldsm_x2(bl[j], bLoB + (jh * 4 + j) * 1152 + k16 * 32);
            }
            #pragma unroll
            for (int i = 0; i < 2; i++)
                #pragma unroll
                for (int j = 0; j < 4; j++) {
                    mma_bf16(acc[i][jh * 4 + j], ah[i], bh[j]);
                    mma_bf16(acc[i][jh * 4 + j], al[i], bh[j]);
                    mma_bf16(acc[i][jh * 4 + j], ah[i], bl[j]);
                }
        }
    }
}

// ---------------- prep kernels ----------------
__global__ void k_prep_w(const float* __restrict__ w, __nv_bfloat16* __restrict__ whi,
                         __nv_bfloat16* __restrict__ wlo)
{
    int idx = blockIdx.x * blockDim.x + threadIdx.x;
    if (idx >= NC * NC * 3) return;
    int co = idx / (NC * 3);
    int kp = idx - co * (NC * 3);
    int t  = kp / NC;
    int ci = kp - t * NC;
    float f = w[(size_t)co * (NC * 3) + ci * 3 + t];
    __nv_bfloat16 h = __float2bfloat16(f);
    whi[idx] = h;
    wlo[idx] = __float2bfloat16(f - __bfloat162float(h));
}
__global__ void k_prep_plain(const float* __restrict__ w, __nv_bfloat16* __restrict__ whi,
                             __nv_bfloat16* __restrict__ wlo)
{
    int idx = blockIdx.x * blockDim.x + threadIdx.x;
    if (idx >= NC * NC) return;
    float f = w[idx];
    __nv_bfloat16 h = __float2bfloat16(f);
    whi[idx] = h;
    wlo[idx] = __float2bfloat16(f - __bfloat162float(h));
}
__global__ void k_prep_scw(const float* __restrict__ w, uint32_t* __restrict__ scw)
{
    int t = blockIdx.x * blockDim.x + threadIdx.x;
    if (t >= SCW_N) return;
    int a    = t % 112;
    int half = (t / 112) & 1;
    int ho   = (t / 224) & 3;
    int s    = (t / 896) % 5;
    int hi   = t / 4480;
    __nv_bfloat16 p[2];
    #pragma unroll
    for (int e = 0; e < 2; e++) {
        int r = a - 33 + e;
        float f = (r >= 0 && r <= 44) ? w[((size_t)(ho * 4 + hi) * 45 + r) * 5 + s] : 0.f;
        __nv_bfloat16 h = __float2bfloat16(f);
        p[e] = half ? __float2bfloat16(f - __bfloat162float(h)) : h;
    }
    scw[t] = packhl(p[0], p[1]);
}
__global__ void k_split(const float* __restrict__ in, __nv_bfloat16* __restrict__ hi,
                        __nv_bfloat16* __restrict__ lo, int n4)
{
    int i = blockIdx.x * blockDim.x + threadIdx.x;
    if (i >= n4) return;
    float4 v = reinterpret_cast<const float4*>(in)[i];
    float f[4] = { v.x, v.y, v.z, v.w };
    __nv_bfloat16 h[4], l[4];
    #pragma unroll
    for (int j = 0; j < 4; j++) {
        h[j] = __float2bfloat16(f[j]);
        l[j] = __float2bfloat16(f[j] - __bfloat162float(h[j]));
    }
    reinterpret_cast<uint2*>(hi)[i] = make_uint2(packhl(h[0], h[1]), packhl(h[2], h[3]));
    reinterpret_cast<uint2*>(lo)[i] = make_uint2(packhl(l[0], l[1]), packhl(l[2], l[3]));
}

// ---------------- conv1d k=3 (implicit GEMM, 128x128 tile, single buffer, 2 CTAs/SM) ----------------
template<int L>
__global__ void __launch_bounds__(256, 2)
k_conv_mma(const __nv_bfloat16* __restrict__ xhi, const __nv_bfloat16* __restrict__ xlo,
           const __nv_bfloat16* __restrict__ whi, const __nv_bfloat16* __restrict__ wlo,
           const float* __restrict__ bias, float* __restrict__ out)
{
    extern __shared__ char sm[];
    const uint32_t smu = smem_u32(sm);
    const int b = blockIdx.z, l0 = blockIdx.x * 128, co0 = blockIdx.y * 128;
    const int tid = threadIdx.x, wid = tid >> 5, lane = tid & 31;
    const int wm = wid & 3, wn = wid >> 2;
    const uint32_t aHiB = smu + C1_A_HI + ((wm * 32 + (lane & 15)) * 72 + (lane >> 4) * 8) * 2;
    const uint32_t aLoB = aHiB + (C1_A_LO - C1_A_HI);
    const uint32_t bHiB = smu + C1_B_HI + ((wn * 64 + (lane & 7)) * 72 + ((lane >> 3) & 1) * 8) * 2;
    const uint32_t bLoB = bHiB + (C1_B_LO - C1_B_HI);
    float acc[2][8][4] = {};
    constexpr int NCH = 24;

    for (int kc = 0; kc < NCH; kc++) {
        const int k0 = kc * 64, t = kc >> 3, ci0 = (kc & 7) * 64;
        // A: 128 rows x 4 quads = 512 slots, 2 per thread
        #pragma unroll
        for (int jj = 0; jj < 2; jj++) {
            int s = tid + jj * 256;
            int rowA = s >> 2, quad = s & 3;
            int l = l0 + rowA + t - 1;
            bool ok = (unsigned)l < (unsigned)L;
            size_t so = ((size_t)b * L + (ok ? l : 0)) * NC + ci0 + quad * 16;
            uint32_t d = smu + C1_A_HI + rowA * 144 + quad * 32;
            cp16(d,      xhi + so,     ok);
            cp16(d + 16, xhi + so + 8, ok);
            cp16(d + (C1_A_LO - C1_A_HI),      xlo + so,     ok);
            cp16(d + (C1_A_LO - C1_A_HI) + 16, xlo + so + 8, ok);
        }
        // B: 128 rows x 8 c8 = 1024 slots, 4 per thread
        #pragma unroll
        for (int j = 0; j < 4; j++) {
            int linear = tid + j * 256;
            int n = linear >> 3, c8 = linear & 7;
            size_t wo = (size_t)(co0 + n) * 1536 + k0 + c8 * 8;
            cp16(smu + C1_B_HI + n * 144 + c8 * 16, whi + wo, true);
            cp16(smu + C1_B_LO + n * 144 + c8 * 16, wlo + wo, true);
        }
        CP_COMMIT();
        CP_WAIT0();
        __syncthreads();
        mma_chunk128(aHiB, aLoB, bHiB, bLoB, acc);
        __syncthreads();
    }

    float* sd = reinterpret_cast<float*>(sm);   // [128 co][132 l]
    const int g = lane >> 2, tq = lane & 3;
    #pragma unroll
    for (int i = 0; i < 2; i++) {
        int ml = wm * 32 + i * 16 + g;
        #pragma unroll
        for (int j = 0; j < 8; j++) {
            int nl = wn * 64 + j * 8 + tq * 2;
            sd[(nl)     * 132 + ml]     = acc[i][j][0];
            sd[(nl + 1) * 132 + ml]     = acc[i][j][1];
            sd[(nl)     * 132 + ml + 8] = acc[i][j][2];
            sd[(nl + 1) * 132 + ml + 8] = acc[i][j][3];
        }
    }
    __syncthreads();
    const int n = tid >> 1, half = tid & 1;
    const float bb = bias[co0 + n];
    float* op = out + ((size_t)b * NC + co0 + n) * L + l0 + half * 64;
    #pragma unroll
    for (int v = 0; v < 64; v += 4) {
        float4 d4 = *reinterpret_cast<float4*>(&sd[n * 132 + half * 64 + v]);
        float4 o;
        float v0 = d4.x + bb, v1 = d4.y + bb, v2 = d4.z + bb, v3 = d4.w + bb;
        o.x = v0 / (1.f + __expf(-v0));
        o.y = v1 / (1.f + __expf(-v1));
        o.z = v2 / (1.f + __expf(-v2));
        o.w = v3 / (1.f + __expf(-v3));
        *reinterpret_cast<float4*>(op + v) = o;
    }
}

// ---------------- plain GEMM (cp.async single buffer, 3 CTAs/SM) ----------------
template<int MODE, int S>
__global__ void __launch_bounds__(256, 3)
k_gemm_mma(const __nv_bfloat16* __restrict__ Ahi, const __nv_bfloat16* __restrict__ Alo,
           const __nv_bfloat16* __restrict__ whi, const __nv_bfloat16* __restrict__ wlo,
           const float* __restrict__ freqs, const float* __restrict__ bias,
           float* __restrict__ out, float* __restrict__ out2)
{
    extern __shared__ char sm[];
    const uint32_t smu = smem_u32(sm);
    const int m0 = blockIdx.y * 64, n0 = blockIdx.x * 128;
    const int tid = threadIdx.x, wid = tid >> 5, lane = tid & 31;
    const int wm = wid & 1, wn = wid >> 1;
    const uint32_t aHiB = smu + SM_A_HI + ((wm * 32 + (lane & 15)) * 72 + (lane >> 4) * 8) * 2;
    const uint32_t aLoB = aHiB + (SM_A_LO - SM_A_HI);
    const uint32_t bHiB = smu + SM_B_HI + ((wn * 32 + (lane & 7)) * 72 + ((lane >> 3) & 1) * 8) * 2;
    const uint32_t bLoB = bHiB + (SM_B_LO - SM_B_HI);
    float acc[2][4][4] = {};
    const int fm = tid >> 2, fq = tid & 3;
    constexpr int NCH = 8;

    for (int kc = 0; kc < NCH; kc++) {
        const int k0 = kc * 64;
        {
            size_t so = (size_t)(m0 + fm) * 512 + k0 + fq * 16;
            uint32_t d = smu + SM_A_HI + fm * 144 + fq * 32;
            cp16(d,      Ahi + so,     true);
            cp16(d + 16, Ahi + so + 8, true);
            cp16(d + (SM_A_LO - SM_A_HI),      Alo + so,     true);
            cp16(d + (SM_A_LO - SM_A_HI) + 16, Alo + so + 8, true);
            #pragma unroll
            for (int j = 0; j < 4; j++) {
                int linear = tid + j * 256;
                int n = linear >> 3, c8 = linear & 7;
                size_t wo = (size_t)(n0 + n) * 512 + k0 + c8 * 8;
                cp16(smu + SM_B_HI + n * 144 + c8 * 16, whi + wo, true);
                cp16(smu + SM_B_LO + n * 144 + c8 * 16, wlo + wo, true);
            }
        }
        CP_COMMIT();
        CP_WAIT0();
        __syncthreads();
        mma_chunk(aHiB, aLoB, bHiB, bLoB, acc);
        __syncthreads();
    }

    const int g = lane >> 2, tq = lane & 3;
    #pragma unroll
    for (int i = 0; i < 2; i++) {
        #pragma unroll
        for (int j = 0; j < 4; j++) {
            int ng = n0 + wn * 32 + j * 8 + tq * 2;
            #pragma unroll
            for (int r = 0; r < 2; r++) {
                int m = m0 + wm * 32 + i * 16 + g + r * 8;
                int bb_ = m / S, l = m - bb_ * S;
                float v0 = acc[i][j][r * 2], v1 = acc[i][j][r * 2 + 1];
                if (MODE == 1) {
                    const float* fp = freqs + ((size_t)bb_ * NSQ + 2 * l + 1) * NHD;
                    v0 += F_PS * fp[ng & (NHD - 1)];
                    v1 += F_PS * fp[(ng + 1) & (NHD - 1)];
                    *reinterpret_cast<float2*>(out + (size_t)m * 512 + ng) = make_float2(v0, v1);
                } else if (MODE == 3) {
                    v0 += bias[ng];
                    v1 += bias[ng + 1];
                    float2 o = make_float2(v0, v1);
                    *reinterpret_cast<float2*>(out + ((size_t)bb_ * NSQ + 2 * l) * 512 + ng)     = o;
                    *reinterpret_cast<float2*>(out + ((size_t)bb_ * NSQ + 2 * l + 1) * 512 + ng) = o;
                } else if (MODE == 4) {
                    if (ng < 512) {
                        const float* fp = freqs + ((size_t)bb_ * S + l) * NHD;
                        v0 += F_PS * fp[ng & (NHD - 1)];
                        v1 += F_PS * fp[(ng + 1) & (NHD - 1)];
                        *reinterpret_cast<float2*>(out + (size_t)m * 512 + ng) = make_float2(v0, v1);
                    } else {
                        *reinterpret_cast<float2*>(out2 + (size_t)m * 512 + (ng - 512)) = make_float2(v0, v1);
                    }
                }
            }
        }
    }
}

// ---------------- gaussian scores (mma), TRANSPOSED bf16-split output ----------------
__global__ void __launch_bounds__(256)
k_scores_mma(const float* __restrict__ q, const float* __restrict__ kmat,
             const float* __restrict__ x2, const float* __restrict__ y2,
             __nv_bfloat16* __restrict__ a0hi, __nv_bfloat16* __restrict__ a0lo)
{
    extern __shared__ char sm[];
    const uint32_t smu = smem_u32(sm);
    const int bh = blockIdx.z, b = bh >> 2, h = bh & 3;
    const int m0 = blockIdx.y * 64, n0 = blockIdx.x * 128;
    const int tid = threadIdx.x, wid = tid >> 5, lane = tid & 31;
    const int wm = wid & 1, wn = wid >> 1;
    const uint32_t aHiB = smu + SM_A_HI + ((wm * 32 + (lane & 15)) * 72 + (lane >> 4) * 8) * 2;
    const uint32_t aLoB = aHiB + (SM_A_LO - SM_A_HI);
    const uint32_t bHiB = smu + SM_B_HI + ((wn * 32 + (lane & 7)) * 72 + ((lane >> 3) & 1) * 8) * 2;
    const uint32_t bLoB = bHiB + (SM_B_LO - SM_B_HI);
    float acc[2][4][4] = {};
    const float* Ab = kmat + ((size_t)b * NSKV + m0) * NC + h * NHD;
    const float* Bb = q    + ((size_t)b * NSQ2 + n0) * NC + h * NHD;
    const int fm = tid >> 2, fq = tid & 3;
    const int fn = tid >> 1, fh = tid & 1;

    for (int kc = 0; kc < 2; kc++) {
        if (kc) __syncthreads();
        const int k0 = kc * 64;
        {
            const float* src = Ab + (size_t)fm * NC + k0 + fq * 16;
            char* dst = sm + SM_A_HI + fm * 144 + fq * 32;
            #pragma unroll
            for (int c2 = 0; c2 < 2; c2++) {
                float f[8];
                float4 v0 = *reinterpret_cast<const float4*>(src + c2 * 8);
                float4 v1 = *reinterpret_cast<const float4*>(src + c2 * 8 + 4);
                f[0]=v0.x; f[1]=v0.y; f[2]=v0.z; f[3]=v0.w;
                f[4]=v1.x; f[5]=v1.y; f[6]=v1.z; f[7]=v1.w;
                uint4 hi, lo; split8(f, hi, lo);
                *reinterpret_cast<uint4*>(dst + c2 * 16) = hi;
                *reinterpret_cast<uint4*>(dst + (SM_A_LO - SM_A_HI) + c2 * 16) = lo;
            }
        }
        {
            const float* src = Bb + (size_t)fn * NC + k0 + fh * 32;
            char* dst = sm + SM_B_HI + fn * 144 + fh * 64;
            #pragma unroll
            for (int c2 = 0; c2 < 4; c2++) {
                float f[8];
                float4 v0 = *reinterpret_cast<const float4*>(src + c2 * 8);
                float4 v1 = *reinterpret_cast<const float4*>(src + c2 * 8 + 4);
                f[0]=v0.x; f[1]=v0.y; f[2]=v0.z; f[3]=v0.w;
                f[4]=v1.x; f[5]=v1.y; f[6]=v1.z; f[7]=v1.w;
                uint4 hi, lo; split8(f, hi, lo);
                *reinterpret_cast<uint4*>(dst + c2 * 16) = hi;
                *reinterpret_cast<uint4*>(dst + (SM_B_LO - SM_B_HI) + c2 * 16) = lo;
            }
        }
        __syncthreads();
        mma_chunk(aHiB, aLoB, bHiB, bLoB, acc);
    }

    const float invtemp = (h == 0) ? 1.f : (h == 1) ? 0.25f : (h == 2) ? (1.f / 7.f) : 0.1f;
    const int g = lane >> 2, tq = lane & 3;
    #pragma unroll
    for (int i = 0; i < 2; i++) {
        #pragma unroll
        for (int j = 0; j < 4; j++) {
            int n = n0 + wn * 32 + j * 8 + tq * 2;
            float xn0 = x2[(size_t)bh * NSQ2 + n];
            float xn1 = x2[(size_t)bh * NSQ2 + n + 1];
            #pragma unroll
            for (int r = 0; r < 2; r++) {
                int m = m0 + wm * 32 + i * 16 + g + r * 8;
                float ym = y2[(size_t)bh * NSKV + m];
                float v0 = -fmaxf(ym + xn0 - 2.f * F_S2 * acc[i][j][r * 2],     0.f) * invtemp;
                float v1 = -fmaxf(ym + xn1 - 2.f * F_S2 * acc[i][j][r * 2 + 1], 0.f) * invtemp;
                __nv_bfloat16 h0 = __float2bfloat16(v0), h1 = __float2bfloat16(v1);
                __nv_bfloat16 l0 = __float2bfloat16(v0 - __bfloat162float(h0));
                __nv_bfloat16 l1 = __float2bfloat16(v1 - __bfloat162float(h1));
                size_t off = ((size_t)bh * NSKV + m) * NSQ2 + n;
                *reinterpret_cast<uint32_t*>(a0hi + off) = packhl(h0, h1);
                *reinterpret_cast<uint32_t*>(a0lo + off) = packhl(l0, l1);
            }
        }
    }
}

// ---------------- Score Conv2d(4->4, 45x5) as Toeplitz GEMM, 512 threads, i-tile 64 ----------------
constexpr int SC_WP_BYTES    = SCW_N * 4;
constexpr int SC_TILE_STRIDE = 240;
constexpr int SC_TILE_BYTES  = 68 * SC_TILE_STRIDE;
constexpr int SC_SMEM        = SC_WP_BYTES + 8 * SC_TILE_BYTES;

__global__ void __launch_bounds__(512, 1)
k_score_conv_mma(const __nv_bfloat16* __restrict__ a0hi, const __nv_bfloat16* __restrict__ a0lo,
                 const uint32_t* __restrict__ scw, const float* __restrict__ sb,
                 const float* __restrict__ mask, float* __restrict__ attn1)
{
    extern __shared__ char sm[];
    const uint32_t smu = smem_u32(sm);
    const int b = blockIdx.z, i0 = blockIdx.y * 64, j0 = blockIdx.x * 64;
    const int tid = threadIdx.x, wid = tid >> 5, lane = tid & 31;
    const int im = (wid & 3) * 16, jn = (wid >> 2) * 16;

    uint32_t* wp = reinterpret_cast<uint32_t*>(sm);
    for (int t = tid; t < SCW_N; t += 512) wp[t] = scw[t];

    for (int t = tid; t < 4 * 68 * 14; t += 512) {
        int u  = t % 14;
        int jr = (t / 14) % 68;
        int hi = t / (14 * 68);
        int j  = j0 - 2 + jr;
        int il = i0 - 24 + u * 8;
        uint4 zh = make_uint4(0, 0, 0, 0), zl = zh;
        if ((unsigned)j < (unsigned)NSKV && (unsigned)il < (unsigned)NSQ2) {
            size_t off = ((size_t)(b * 4 + hi) * NSKV + j) * NSQ2 + il;
            zh = *reinterpret_cast<const uint4*>(a0hi + off);
            zl = *reinterpret_cast<const uint4*>(a0lo + off);
        }
        char* dh = sm + SC_WP_BYTES + (hi * 2) * SC_TILE_BYTES + jr * SC_TILE_STRIDE + u * 16;
        *reinterpret_cast<uint4*>(dh) = zh;
        *reinterpret_cast<uint4*>(dh + SC_TILE_BYTES) = zl;
    }
    __syncthreads();

    float acc[4][2][4] = {};
    const int q = lane & 3, g = lane >> 2;
    const int ip_base = 2 * q - g + 31;
    const int coff = im >> 4;
    const uint32_t lofs = (lane & 7) * SC_TILE_STRIDE + ((lane >> 3) & 1) * 16;

    for (int hi = 0; hi < 4; hi++) {
        const uint32_t tbase = smu + SC_WP_BYTES + (hi * 2) * SC_TILE_BYTES;
        #pragma unroll
        for (int s = 0; s < 5; s++) {
            const uint32_t* wpb = wp + ((hi * 5 + s) * 4) * 224;
            const uint32_t rowb = tbase + (jn + s) * SC_TILE_STRIDE + lofs + coff * 32;

            uint32_t bh[4][4], bl[4][4];
            #pragma unroll
            for (int c = 0; c < 4; c++) {
                uint32_t cb = rowb + c * 32;
                ldsm_x2(&bh[c][0], cb);
                ldsm_x2(&bh[c][2], cb + 8 * SC_TILE_STRIDE);
                ldsm_x2(&bl[c][0], cb + SC_TILE_BYTES);
                ldsm_x2(&bl[c][2], cb + SC_TILE_BYTES + 8 * SC_TILE_STRIDE);
            }

            #pragma unroll
            for (int ho = 0; ho < 4; ho++) {
                const uint32_t* wph = wpb + ho * 224;
                const uint32_t* wpl = wph + 112;
                uint32_t Wh[9], Wl[9];
                #pragma unroll
                for (int k = 0; k < 9; k++) {
                    Wh[k] = wph[ip_base - 8 + 8 * k];
                    Wl[k] = wpl[ip_base - 8 + 8 * k];
                }
                #pragma unroll
                for (int c = 0; c < 4; c++) {
                    uint32_t Ah[4] = { Wh[2*c+1], Wh[2*c], Wh[2*c+2], Wh[2*c+1] };
                    uint32_t Al[4] = { Wl[2*c+1], Wl[2*c], Wl[2*c+2], Wl[2*c+1] };
                    mma_bf16(acc[ho][0], Ah, &bh[c][0]);
                    mma_bf16(acc[ho][1], Ah, &bh[c][2]);
                    mma_bf16(acc[ho][0], Al, &bh[c][0]);
                    mma_bf16(acc[ho][1], Al, &bh[c][2]);
                    mma_bf16(acc[ho][0], Ah, &bl[c][0]);
                    mma_bf16(acc[ho][1], Ah, &bl[c][2]);
                }
            }
        }
    }

    #pragma unroll
    for (int ho = 0; ho < 4; ho++) {
        const float bb = sb[ho];
        const __nv_bfloat16* th = reinterpret_cast<const __nv_bfloat16*>(
            sm + SC_WP_BYTES + (ho * 2) * SC_TILE_BYTES);
        const __nv_bfloat16* tl = reinterpret_cast<const __nv_bfloat16*>(
            sm + SC_WP_BYTES + (ho * 2) * SC_TILE_BYTES + SC_TILE_BYTES);
        #pragma unroll
        for (int nf = 0; nf < 2; nf++) {
            int j  = j0 + jn + nf * 8 + q * 2;
            int jr = j - j0 + 2;
            #pragma unroll
            for (int r = 0; r < 2; r++) {
                int i  = i0 + im + g + r * 8;
                int ii = im + g + r * 8 + 24;
                float res0 = __bfloat162float(th[jr * 120 + ii]) + __bfloat162float(tl[jr * 120 + ii]);
                float res1 = __bfloat162float(th[(jr + 1) * 120 + ii]) + __bfloat162float(tl[(jr + 1) * 120 + ii]);
                float2 mk = *reinterpret_cast<const float2*>(mask + ((size_t)b * NSQ2 + i) * NSKV + j);
                float v0 = acc[ho][nf][r * 2]     + res0 + bb + mk.x;
                float v1 = acc[ho][nf][r * 2 + 1] + res1 + bb + mk.y;
                *reinterpret_cast<float2*>(attn1 + ((size_t)(b * 4 + ho) * NSQ2 + i) * NSKV + j) =
                    make_float2(v0, v1);
            }
        }
    }
}

// ---------------- attn @ v (cp.async single buffer, 3 CTAs/SM) ----------------
__global__ void __launch_bounds__(256, 3)
k_av_mma(const __nv_bfloat16* __restrict__ a1hi, const __nv_bfloat16* __restrict__ a1lo,
         const __nv_bfloat16* __restrict__ vthi, const __nv_bfloat16* __restrict__ vtlo,
         __nv_bfloat16* __restrict__ ybhi, __nv_bfloat16* __restrict__ yblo)
{
    extern __shared__ char sm[];
    const uint32_t smu = smem_u32(sm);
    const int bh = blockIdx.y, b = bh >> 2, h = bh & 3;
    const int m0 = blockIdx.x * 64;
    const int tid = threadIdx.x, wid = tid >> 5, lane = tid & 31;
    const int wm = wid & 1, wn = wid >> 1;
    const uint32_t aHiB = smu + SM_A_HI + ((wm * 32 + (lane & 15)) * 72 + (lane >> 4) * 8) * 2;
    const uint32_t aLoB = aHiB + (SM_A_LO - SM_A_HI);
    const uint32_t bHiB = smu + SM_B_HI + ((wn * 32 + (lane & 7)) * 72 + ((lane >> 3) & 1) * 8) * 2;
    const uint32_t bLoB = bHiB + (SM_B_LO - SM_B_HI);
    float acc[2][4][4] = {};
    const __nv_bfloat16* Ah = a1hi + ((size_t)bh * NSQ2 + m0) * NSKV;
    const __nv_bfloat16* Al = a1lo + ((size_t)bh * NSQ2 + m0) * NSKV;
    const __nv_bfloat16* Bh = vthi + ((size_t)b * NC + h * NHD) * NSKV;
    const __nv_bfloat16* Bl = vtlo + ((size_t)b * NC + h * NHD) * NSKV;
    const int fm = tid >> 2, fq = tid & 3;
    const int fn = tid >> 1, fh = tid & 1;
    constexpr int NCH = 8;

    for (int kc = 0; kc < NCH; kc++) {
        const int k0 = kc * 64;
        {
            size_t so = (size_t)fm * NSKV + k0 + fq * 16;
            uint32_t d = smu + SM_A_HI + fm * 144 + fq * 32;
            cp16(d,      Ah + so,     true);
            cp16(d + 16, Ah + so + 8, true);
            cp16(d + (SM_A_LO - SM_A_HI),      Al + so,     true);
            cp16(d + (SM_A_LO - SM_A_HI) + 16, Al + so + 8, true);
            size_t bo = (size_t)fn * NSKV + k0 + fh * 32;
            uint32_t db = smu + SM_B_HI + fn * 144 + fh * 64;
            #pragma unroll
            for (int c = 0; c < 4; c++) {
                cp16(db + c * 16, Bh + bo + c * 8, true);
                cp16(db + (SM_B_LO - SM_B_HI) + c * 16, Bl + bo + c * 8, true);
            }
        }
        CP_COMMIT();
        CP_WAIT0();
        __syncthreads();
        mma_chunk(aHiB, aLoB, bHiB, bLoB, acc);
        __syncthreads();
    }

    const int g = lane >> 2, tq = lane & 3;
    #pragma unroll
    for (int i = 0; i < 2; i++)
        #pragma unroll
        for (int j = 0; j < 4; j++) {
            int n = wn * 32 + j * 8 + tq * 2;
            #pragma unroll
            for (int r = 0; r < 2; r++) {
                int m = m0 + wm * 32 + i * 16 + g + r * 8;
                float v0 = acc[i][j][r * 2], v1 = acc[i][j][r * 2 + 1];
                __nv_bfloat16 h0 = __float2bfloat16(v0), h1 = __float2bfloat16(v1);
                __nv_bfloat16 l0 = __float2bfloat16(v0 - __bfloat162float(h0));
                __nv_bfloat16 l1 = __float2bfloat16(v1 - __bfloat162float(h1));
                size_t off = ((size_t)b * NSQ2 + m) * NC + h * NHD + n;
                *reinterpret_cast<uint32_t*>(ybhi + off) = packhl(h0, h1);
                *reinterpret_cast<uint32_t*>(yblo + off) = packhl(l0, l1);
            }
        }
}

// ---------------- elementwise / reductions ----------------
template<int L>
__global__ void k_layernorm_ch(float* __restrict__ buf, const float* __restrict__ g,
                               const float* __restrict__ bp)
{
    int col = blockIdx.x * blockDim.x + threadIdx.x;
    if (col >= NB * L) return;
    int b = col / L, l = col - b * L;
    float* p = buf + (size_t)b * NC * L + l;
    float s = 0.f, ss = 0.f;
    #pragma unroll 8
    for (int c = 0; c < NC; c++) {
        float v = p[(size_t)c * L];
        s += v; ss += v * v;
    }
    float mean = s * (1.f / NC);
    float inv  = rsqrtf(ss * (1.f / NC) - mean * mean + 1e-5f);
    #pragma unroll 8
    for (int c = 0; c < NC; c++) {
        float v = p[(size_t)c * L];
        p[(size_t)c * L] = (v - mean) * inv * g[c] + bp[c];
    }
}

template<int L>
__global__ void k_maxpool(const float* __restrict__ in, float* __restrict__ out)
{
    const int LO = L / 2;
    int idx = blockIdx.x * blockDim.x + threadIdx.x;
    if (idx >= NB * NC * LO) return;
    int lo = idx % LO;
    int bc = idx / LO;
    const float* p = in + (size_t)bc * L;
    int l = 2 * lo;
    float m = p[l];
    if (l - 1 >= 0) m = fmaxf(m, p[l - 1]);
    if (l + 1 < L)  m = fmaxf(m, p[l + 1]);
    out[idx] = m;
}

__global__ void k_transpose_cl_sp(const float* __restrict__ in,
                                  __nv_bfloat16* __restrict__ ohi,
                                  __nv_bfloat16* __restrict__ olo)
{
    __shared__ float s[32][33];
    const int b = blockIdx.z, c0 = blockIdx.y * 32, l0 = blockIdx.x * 32;
    for (int i = threadIdx.y; i < 32; i += 8)
        s[i][threadIdx.x] = in[((size_t)b * NC + c0 + i) * NSQ2 + l0 + threadIdx.x];
    __syncthreads();
    for (int i = threadIdx.y; i < 32; i += 8) {
        float v = s[threadIdx.x][i];
        __nv_bfloat16 h = __float2bfloat16(v);
        size_t off = ((size_t)b * NSQ2 + l0 + i) * NC + c0 + threadIdx.x;
        ohi[off] = h;
        olo[off] = __float2bfloat16(v - __bfloat162float(h));
    }
}

__global__ void k_transpose_v_sp(const float* __restrict__ in,
                                 __nv_bfloat16* __restrict__ ohi,
                                 __nv_bfloat16* __restrict__ olo)
{
    __shared__ float s[32][33];
    const int b = blockIdx.z, r0 = blockIdx.y * 32, c0 = blockIdx.x * 32;
    for (int i = threadIdx.y; i < 32; i += 8)
        s[i][threadIdx.x] = in[((size_t)b * 512 + r0 + i) * 512 + c0 + threadIdx.x];
    __syncthreads();
    for (int i = threadIdx.y; i < 32; i += 8) {
        float v = s[threadIdx.x][i];
        __nv_bfloat16 h = __float2bfloat16(v);
        size_t off = ((size_t)b * 512 + c0 + i) * 512 + r0 + threadIdx.x;
        ohi[off] = h;
        olo[off] = __float2bfloat16(v - __bfloat162float(h));
    }
}

__global__ void k_build_qx_sp(const float* __restrict__ x0, const float* __restrict__ x1,
                              __nv_bfloat16* __restrict__ ohi, __nv_bfloat16* __restrict__ olo)
{
    __shared__ float s[32][33];
    const int b = blockIdx.z, c0 = blockIdx.y * 32, l0 = blockIdx.x * 32;
    for (int i = threadIdx.y; i < 32; i += 8) {
        int l = l0 + threadIdx.x;
        s[i][threadIdx.x] = x0[((size_t)b * NC + c0 + i) * NSQ2 + l]
                          + x1[((size_t)b * NC + c0 + i) * NSQ4 + (l >> 1)];
    }
    __syncthreads();
    for (int i = threadIdx.y; i < 32; i += 8) {
        float v = s[threadIdx.x][i];
        __nv_bfloat16 h = __float2bfloat16(v);
        size_t off = ((size_t)b * NSQ2 + l0 + i) * NC + c0 + threadIdx.x;
        ohi[off] = h;
        olo[off] = __float2bfloat16(v - __bfloat162float(h));
    }
}

template<int S>
__global__ void k_row_norms(const float* __restrict__ x, float* __restrict__ o)
{
    int gid  = blockIdx.x * (blockDim.x / 32) + (threadIdx.x >> 5);
    int lane = threadIdx.x & 31;
    if (gid >= NB * NH * S) return;
    int b = gid / (NH * S);
    int r = gid - b * NH * S;
    int h = r / S, i = r - h * S;
    const float* p = x + ((size_t)b * S + i) * NC + h * NHD;
    float s = 0.f;
    #pragma unroll
    for (int d = lane; d < NHD; d += 32) s += p[d] * p[d];
    #pragma unroll
    for (int off = 16; off; off >>= 1) s += __shfl_xor_sync(0xffffffffu, s, off);
    if (lane == 0) o[gid] = s * F_S2;
}

__global__ void __launch_bounds__(128)
k_softmax_prior(const float* __restrict__ attn, const float* __restrict__ prior,
                __nv_bfloat16* __restrict__ a1hi, __nv_bfloat16* __restrict__ a1lo,
                float* __restrict__ oattn, int write_attn)
{
    __shared__ float red[4];
    const int row = blockIdx.x;
    const int bh = row / NSQ2;
    const int i  = row - bh * NSQ2;
    const int b  = bh >> 2;
    const float* p = attn + (size_t)row * NSKV;
    const float* pr = prior + ((size_t)b * NSQ + 2 * i + 1) * NSKV;
    const int t = threadIdx.x;

    float v[4];
    #pragma unroll
    for (int j = 0; j < 4; j++) v[j] = p[t + 128 * j];

    float mx = fmaxf(fmaxf(v[0], v[1]), fmaxf(v[2], v[3]));
    #pragma unroll
    for (int off = 16; off; off >>= 1) mx = fmaxf(mx, __shfl_xor_sync(0xffffffffu, mx, off));
    if ((t & 31) == 0) red[t >> 5] = mx;
    __syncthreads();
    mx = fmaxf(fmaxf(red[0], red[1]), fmaxf(red[2], red[3]));
    __syncthreads();

    float e[4], s = 0.f;
    #pragma unroll
    for (int j = 0; j < 4; j++) { e[j] = __expf(v[j] - mx); s += e[j]; }
    #pragma unroll
    for (int off = 16; off; off >>= 1) s += __shfl_xor_sync(0xffffffffu, s, off);
    if ((t & 31) == 0) red[t >> 5] = s;
    __syncthreads();
    s = red[0] + red[1] + red[2] + red[3];
    __syncthreads();
    float inv = 1.f / s;

    float w[4], s2 = 0.f;
    #pragma unroll
    for (int j = 0; j < 4; j++) {
        w[j] = fmaxf(e[j] * inv, 1e-8f) * fmaxf(pr[t + 128 * j], 1e-8f);
        s2 += w[j];
    }
    #pragma unroll
    for (int off = 16; off; off >>= 1) s2 += __shfl_xor_sync(0xffffffffu, s2, off);
    if ((t & 31) == 0) red[t >> 5] = s2;
    __syncthreads();
    s2 = red[0] + red[1] + red[2] + red[3];
    float i2 = 1.f / (s2 + 1e-8f);

    #pragma unroll
    for (int j = 0; j < 4; j++) {
        float o = w[j] * i2;
        __nv_bfloat16 h = __float2bfloat16(o);
        size_t po = (size_t)row * NSKV + t + 128 * j;
        a1hi[po] = h;
        a1lo[po] = __float2bfloat16(o - __bfloat162float(h));
        if (write_attn) {
            size_t o0 = ((size_t)bh * NSQ + 2 * i) * NSKV + t + 128 * j;
            oattn[o0] = o;
            oattn[o0 + NSKV] = o;
        }
    }
}

// ---------------- host launcher ----------------
extern "C" void kernel_launch(void* const* d_in, const int* in_sizes, int n_in,
                              void* d_out, int out_size)
{
    (void)in_sizes; (void)n_in;
    const float* q_x    = (const float*)d_in[0];
    const float* kv_x   = (const float*)d_in[1];
    const float* qfreq  = (const float*)d_in[2];
    const float* kfreq  = (const float*)d_in[3];
    const float* mask   = (const float*)d_in[4];
    const float* prior  = (const float*)d_in[5];
    const float* qds_cw = (const float*)d_in[6];
    const float* qds_cb = (const float*)d_in[7];
    const float* qds_g  = (const float*)d_in[8];
    const float* qds_b  = (const float*)d_in[9];
    const float* qp_cw  = (const float*)d_in[10];
    const float* qp_cb  = (const float*)d_in[11];
    const float* qp_g   = (const float*)d_in[12];
    const float* qp_b   = (const float*)d_in[13];
    const float* wq     = (const float*)d_in[14];
    const float* wk     = (const float*)d_in[15];
    const float* wv     = (const float*)d_in[16];
    const float* sw     = (const float*)d_in[17];
    const float* sb     = (const float*)d_in[18];
    const float* pw     = (const float*)d_in[19];
    const float* pb     = (const float*)d_in[20];

    float* out = (float*)d_out;
    const size_t XOUT_N = (size_t)NB * NSQ * NC;
    const size_t ATT_N  = (size_t)NB * NH * NSQ * NSKV;
    int write_attn = ((size_t)out_size >= XOUT_N + ATT_N) ? 1 : 0;
    float* out_attn = out + XOUT_N;

    void* pv;
    cudaGetSymbolAddress(&pv, g_tmp); float* tmp = (float*)pv;
    cudaGetSymbolAddress(&pv, g_x0);  float* x0  = (float*)pv;
    cudaGetSymbolAddress(&pv, g_x1);  float* x1  = (float*)pv;
    cudaGetSymbolAddress(&pv, g_qx);  float* qx  = (float*)pv;
    cudaGetSymbolAddress(&pv, g_q);   float* qb  = (float*)pv;
    cudaGetSymbolAddress(&pv, g_k);   float* kb  = (float*)pv;
    cudaGetSymbolAddress(&pv, g_v);   float* vb  = (float*)pv;
    cudaGetSymbolAddress(&pv, g_x2);  float* x2b = (float*)pv;
    cudaGetSymbolAddress(&pv, g_y2);  float* y2b = (float*)pv;
    cudaGetSymbolAddress(&pv, g_a0);  float* a0  = (float*)pv;
    cudaGetSymbolAddress(&pv, g_a1);  float* a1  = (float*)pv;
    cudaGetSymbolAddress(&pv, g_y);   float* yb  = (float*)pv;
    cudaGetSymbolAddress(&pv, g_inqh);  __nv_bfloat16* inqh  = (__nv_bfloat16*)pv;
    cudaGetSymbolAddress(&pv, g_inql);  __nv_bfloat16* inql  = (__nv_bfloat16*)pv;
    cudaGetSymbolAddress(&pv, g_inkvh); __nv_bfloat16* inkvh = (__nv_bfloat16*)pv;
    cudaGetSymbolAddress(&pv, g_inkvl); __nv_bfloat16* inkvl = (__nv_bfloat16*)pv;
    cudaGetSymbolAddress(&pv, g_whi1); __nv_bfloat16* whi1 = (__nv_bfloat16*)pv;
    cudaGetSymbolAddress(&pv, g_wlo1); __nv_bfloat16* wlo1 = (__nv_bfloat16*)pv;
    cudaGetSymbolAddress(&pv, g_whi2); __nv_bfloat16* whi2 = (__nv_bfloat16*)pv;
    cudaGetSymbolAddress(&pv, g_wlo2); __nv_bfloat16* wlo2 = (__nv_bfloat16*)pv;
    cudaGetSymbolAddress(&pv, g_pwhi); __nv_bfloat16* pwhi = (__nv_bfloat16*)pv;
    cudaGetSymbolAddress(&pv, g_pwlo); __nv_bfloat16* pwlo = (__nv_bfloat16*)pv;
    cudaGetSymbolAddress(&pv, g_scw);  uint32_t* scw = (uint32_t*)pv;

    __nv_bfloat16* a0hi = (__nv_bfloat16*)a0;
    __nv_bfloat16* a0lo = a0hi + (size_t)NB * NH * NSQ2 * NSKV;
    __nv_bfloat16* a1shi = a0hi;
    __nv_bfloat16* a1slo = a0lo;
    __nv_bfloat16* x0th = (__nv_bfloat16*)qx;
    __nv_bfloat16* x0tl = x0th + (size_t)NB * NSQ2 * NC;
    __nv_bfloat16* qxh  = x0th;
    __nv_bfloat16* qxl  = x0tl;
    __nv_bfloat16* vth  = (__nv_bfloat16*)tmp;
    __nv_bfloat16* vtl  = vth + (size_t)NB * NC * NSKV;
    __nv_bfloat16* ybh  = (__nv_bfloat16*)yb;
    __nv_bfloat16* ybl  = ybh + (size_t)NB * NSQ2 * NC;

    auto setsm = [](const void* f, int sz) {
        cudaFuncSetAttribute(f, cudaFuncAttributeMaxDynamicSharedMemorySize, sz);
        cudaFuncSetAttribute(f, cudaFuncAttributePreferredSharedMemoryCarveout, 100);
    };
    setsm((const void*)k_conv_mma<NSQ>,  C1_TOT);
    setsm((const void*)k_conv_mma<NSQ2>, C1_TOT);
    setsm((const void*)k_gemm_mma<1, NSQ2>, SM_TOT);
    setsm((const void*)k_gemm_mma<4, NSKV>, SM_TOT);
    setsm((const void*)k_gemm_mma<3, NSQ2>, SM_TOT);
    setsm((const void*)k_scores_mma, SM_TOT);
    setsm((const void*)k_av_mma, SM_TOT);
    setsm((const void*)k_score_conv_mma, SC_SMEM);

    // launch order: index 3 (ncu capture slot) = big conv
    k_prep_w<<<(NC * NC * 3 + 255) / 256, 256>>>(qds_cw, whi1, wlo1);                              // 0
    k_split<<<(NB * NSQ * NC / 4 + 255) / 256, 256>>>(q_x, inqh, inql, NB * NSQ * NC / 4);         // 1
    k_prep_w<<<(NC * NC * 3 + 255) / 256, 256>>>(qp_cw,  whi2, wlo2);                              // 2
    k_conv_mma<NSQ><<<dim3(NSQ / 128, 4, NB), 256, C1_TOT>>>(inqh, inql, whi1, wlo1, qds_cb, tmp); // 3

    k_split<<<(NB * NSKV * NC / 4 + 255) / 256, 256>>>(kv_x, inkvh, inkvl, NB * NSKV * NC / 4);
    k_prep_plain<<<(NC * NC + 255) / 256, 256>>>(wq, pwhi, pwlo);
    k_prep_plain<<<(NC * NC + 255) / 256, 256>>>(wk, pwhi + NC * NC, pwlo + NC * NC);
    k_prep_plain<<<(NC * NC + 255) / 256, 256>>>(wv, pwhi + 2 * NC * NC, pwlo + 2 * NC * NC);
    k_prep_plain<<<(NC * NC + 255) / 256, 256>>>(pw, pwhi + 3 * NC * NC, pwlo + 3 * NC * NC);
    k_prep_scw<<<(SCW_N + 255) / 256, 256>>>(sw, scw);

    k_layernorm_ch<NSQ ><<<(NB * NSQ  + 127) / 128, 128>>>(tmp, qds_g, qds_b);
    k_maxpool<NSQ ><<<(NB * NC * NSQ2 + 255) / 256, 256>>>(tmp, x0);

    k_transpose_cl_sp<<<dim3(NSQ2 / 32, NC / 32, NB), dim3(32, 8)>>>(x0, x0th, x0tl);
    k_conv_mma<NSQ2><<<dim3(NSQ2 / 128, 4, NB), 256, C1_TOT>>>(x0th, x0tl, whi2, wlo2, qp_cb, tmp);
    k_layernorm_ch<NSQ2><<<(NB * NSQ2 + 127) / 128, 128>>>(tmp, qp_g, qp_b);
    k_maxpool<NSQ2><<<(NB * NC * NSQ4 + 255) / 256, 256>>>(tmp, x1);

    k_build_qx_sp<<<dim3(NSQ2 / 32, NC / 32, NB), dim3(32, 8)>>>(x0, x1, qxh, qxl);

    k_gemm_mma<1, NSQ2><<<dim3(4, NB * NSQ2 / 64), 256, SM_TOT>>>(qxh, qxl, pwhi, pwlo, qfreq, nullptr, qb, nullptr);
    k_gemm_mma<4, NSKV><<<dim3(8, NB * NSKV / 64), 256, SM_TOT>>>(inkvh, inkvl, pwhi + NC * NC, pwlo + NC * NC, kfreq, nullptr, kb, vb);

    k_transpose_v_sp<<<dim3(16, 16, NB), dim3(32, 8)>>>(vb, vth, vtl);

    k_row_norms<NSQ2><<<NB * NH * NSQ2 / 8, 256>>>(qb, x2b);
    k_row_norms<NSKV><<<NB * NH * NSKV / 8, 256>>>(kb, y2b);
    k_scores_mma<<<dim3(NSQ2 / 128, NSKV / 64, NB * NH), 256, SM_TOT>>>(qb, kb, x2b, y2b, a0hi, a0lo);

    k_score_conv_mma<<<dim3(NSKV / 64, NSQ2 / 64, NB), 512, SC_SMEM>>>(a0hi, a0lo, scw, sb, mask, a1);

    k_softmax_prior<<<NB * NH * NSQ2, 128>>>(a1, prior, a1shi, a1slo, out_attn, write_attn);

    k_av_mma<<<dim3(16, NB * NH), 256, SM_TOT>>>(a1shi, a1slo, vth, vtl, ybh, ybl);
    k_gemm_mma<3, NSQ2><<<dim3(4, NB * NSQ2 / 64), 256, SM_TOT>>>(ybh, ybl, pwhi + 3 * NC * NC, pwlo + 3 * NC * NC, nullptr, pb, out, nullptr);
}

// round 16
// speedup vs baseline: 1.0297x; 1.0297x over previous
#include <cuda_runtime.h>
#include <cuda_bf16.h>
#include <cstdint>
#include <cstddef>
#include <math.h>

constexpr int NB=8, NC=512, NSQ=2048, NSQ2=1024, NSQ4=512, NSKV=512, NH=4, NHD=128;
constexpr float F_PS = 0.31622776601683794f;
constexpr float F_S2 = 1.0f / 128.0f;

__device__ float g_tmp[NB * NC * NSQ];
__device__ float g_x0 [NB * NC * NSQ2];
__device__ float g_x1 [NB * NC * NSQ4];
__device__ float g_qx [NB * NSQ2 * NC];
__device__ float g_q  [NB * NSQ2 * NC];   // overlay: q bf16 hi/lo
__device__ float g_k  [NB * NSKV * NC];   // overlay: k bf16 hi/lo
__device__ float g_v  [NB * NSKV * NC];
__device__ float g_x2 [NB * NH * NSQ2];
__device__ float g_y2 [NB * NH * NSKV];
__device__ float g_a0 [NB * NH * NSQ2 * NSKV];
__device__ float g_a1 [NB * NH * NSQ2 * NSKV];
__device__ float g_y  [NB * NSQ2 * NC];
__device__ __nv_bfloat16 g_inqh [NB * NSQ * NC];
__device__ __nv_bfloat16 g_inql [NB * NSQ * NC];
__device__ __nv_bfloat16 g_inkvh[NB * NSKV * NC];
__device__ __nv_bfloat16 g_inkvl[NB * NSKV * NC];
__device__ __nv_bfloat16 g_whi1[NC * NC * 3];
__device__ __nv_bfloat16 g_wlo1[NC * NC * 3];
__device__ __nv_bfloat16 g_whi2[NC * NC * 3];
__device__ __nv_bfloat16 g_wlo2[NC * NC * 3];
__device__ __nv_bfloat16 g_pwhi[4 * NC * NC];
__device__ __nv_bfloat16 g_pwlo[4 * NC * NC];
constexpr int SCW_N = 4 * 5 * 4 * 2 * 112;
__device__ uint32_t g_scw[SCW_N];

__device__ __forceinline__ uint32_t smem_u32(const void* p) {
    uint32_t a;
    asm("{ .reg .u64 t; cvta.to.shared.u64 t, %1; cvt.u32.u64 %0, t; }" : "=r"(a) : "l"(p));
    return a;
}
__device__ __forceinline__ void ldsm_x4(uint32_t* r, uint32_t addr) {
    asm volatile("ldmatrix.sync.aligned.m8n8.x4.shared.b16 {%0,%1,%2,%3}, [%4];"
        : "=r"(r[0]), "=r"(r[1]), "=r"(r[2]), "=r"(r[3]) : "r"(addr));
}
__device__ __forceinline__ void ldsm_x2(uint32_t* r, uint32_t addr) {
    asm volatile("ldmatrix.sync.aligned.m8n8.x2.shared.b16 {%0,%1}, [%2];"
        : "=r"(r[0]), "=r"(r[1]) : "r"(addr));
}
__device__ __forceinline__ void mma_bf16(float* c, const uint32_t* a, const uint32_t* b) {
    asm volatile("mma.sync.aligned.m16n8k16.row.col.f32.bf16.bf16.f32 "
        "{%0,%1,%2,%3}, {%4,%5,%6,%7}, {%8,%9}, {%0,%1,%2,%3};"
        : "+f"(c[0]), "+f"(c[1]), "+f"(c[2]), "+f"(c[3])
        : "r"(a[0]), "r"(a[1]), "r"(a[2]), "r"(a[3]), "r"(b[0]), "r"(b[1]));
}
__device__ __forceinline__ uint32_t packhl(__nv_bfloat16 a, __nv_bfloat16 b) {
    uint16_t ua = *reinterpret_cast<uint16_t*>(&a);
    uint16_t ub = *reinterpret_cast<uint16_t*>(&b);
    return (uint32_t)ua | ((uint32_t)ub << 16);
}
__device__ __forceinline__ void split8(const float* f, uint4& hi, uint4& lo) {
    __nv_bfloat16 h[8], l[8];
    #pragma unroll
    for (int i = 0; i < 8; i++) {
        h[i] = __float2bfloat16(f[i]);
        l[i] = __float2bfloat16(f[i] - __bfloat162float(h[i]));
    }
    hi = make_uint4(packhl(h[0],h[1]), packhl(h[2],h[3]), packhl(h[4],h[5]), packhl(h[6],h[7]));
    lo = make_uint4(packhl(l[0],l[1]), packhl(l[2],l[3]), packhl(l[4],l[5]), packhl(l[6],l[7]));
}
__device__ __forceinline__ void cp16(uint32_t d, const void* s, bool ok) {
    int sz = ok ? 16 : 0;
    asm volatile("cp.async.cg.shared.global [%0], [%1], 16, %2;" :: "r"(d), "l"(s), "r"(sz) : "memory");
}
#define CP_COMMIT() asm volatile("cp.async.commit_group;" ::: "memory")
#define CP_WAIT0()  asm volatile("cp.async.wait_group 0;" ::: "memory")

constexpr int SM_A_HI = 0, SM_A_LO = 9216, SM_B_HI = 18432, SM_B_LO = 36864, SM_TOT = 55296;

__device__ __forceinline__ void mma_chunk(uint32_t aHiB, uint32_t aLoB,
                                          uint32_t bHiB, uint32_t bLoB,
                                          float acc[2][4][4]) {
    #pragma unroll
    for (int k16 = 0; k16 < 4; k16++) {
        uint32_t ah[2][4], al[2][4], bh[4][2], bl[4][2];
        #pragma unroll
        for (int i = 0; i < 2; i++) {
            ldsm_x4(ah[i], aHiB + i * 2304 + k16 * 32);
            ldsm_x4(al[i], aLoB + i * 2304 + k16 * 32);
        }
        #pragma unroll
        for (int j = 0; j < 4; j++) {
            ldsm_x2(bh[j], bHiB + j * 1152 + k16 * 32);
            ldsm_x2(bl[j], bLoB + j * 1152 + k16 * 32);
        }
        #pragma unroll
        for (int i = 0; i < 2; i++)
            #pragma unroll
            for (int j = 0; j < 4; j++) {
                mma_bf16(acc[i][j], ah[i], bh[j]);
                mma_bf16(acc[i][j], al[i], bh[j]);
                mma_bf16(acc[i][j], ah[i], bl[j]);
            }
    }
}

// ---------------- prep kernels ----------------
__global__ void k_prep_w(const float* __restrict__ w, __nv_bfloat16* __restrict__ whi,
                         __nv_bfloat16* __restrict__ wlo)
{
    int idx = blockIdx.x * blockDim.x + threadIdx.x;
    if (idx >= NC * NC * 3) return;
    int co = idx / (NC * 3);
    int kp = idx - co * (NC * 3);
    int t  = kp / NC;
    int ci = kp - t * NC;
    float f = w[(size_t)co * (NC * 3) + ci * 3 + t];
    __nv_bfloat16 h = __float2bfloat16(f);
    whi[idx] = h;
    wlo[idx] = __float2bfloat16(f - __bfloat162float(h));
}
__global__ void k_prep_plain(const float* __restrict__ w, __nv_bfloat16* __restrict__ whi,
                             __nv_bfloat16* __restrict__ wlo)
{
    int idx = blockIdx.x * blockDim.x + threadIdx.x;
    if (idx >= NC * NC) return;
    float f = w[idx];
    __nv_bfloat16 h = __float2bfloat16(f);
    whi[idx] = h;
    wlo[idx] = __float2bfloat16(f - __bfloat162float(h));
}
__global__ void k_prep_scw(const float* __restrict__ w, uint32_t* __restrict__ scw)
{
    int t = blockIdx.x * blockDim.x + threadIdx.x;
    if (t >= SCW_N) return;
    int a    = t % 112;
    int half = (t / 112) & 1;
    int ho   = (t / 224) & 3;
    int s    = (t / 896) % 5;
    int hi   = t / 4480;
    __nv_bfloat16 p[2];
    #pragma unroll
    for (int e = 0; e < 2; e++) {
        int r = a - 33 + e;
        float f = (r >= 0 && r <= 44) ? w[((size_t)(ho * 4 + hi) * 45 + r) * 5 + s] : 0.f;
        __nv_bfloat16 h = __float2bfloat16(f);
        p[e] = half ? __float2bfloat16(f - __bfloat162float(h)) : h;
    }
    scw[t] = packhl(p[0], p[1]);
}
__global__ void k_split(const float* __restrict__ in, __nv_bfloat16* __restrict__ hi,
                        __nv_bfloat16* __restrict__ lo, int n4)
{
    int i = blockIdx.x * blockDim.x + threadIdx.x;
    if (i >= n4) return;
    float4 v = reinterpret_cast<const float4*>(in)[i];
    float f[4] = { v.x, v.y, v.z, v.w };
    __nv_bfloat16 h[4], l[4];
    #pragma unroll
    for (int j = 0; j < 4; j++) {
        h[j] = __float2bfloat16(f[j]);
        l[j] = __float2bfloat16(f[j] - __bfloat162float(h[j]));
    }
    reinterpret_cast<uint2*>(hi)[i] = make_uint2(packhl(h[0], h[1]), packhl(h[2], h[3]));
    reinterpret_cast<uint2*>(lo)[i] = make_uint2(packhl(l[0], l[1]), packhl(l[2], l[3]));
}

// ---------------- conv1d k=3 (implicit GEMM, cp.async single buffer, 3 CTAs/SM) ----------------
template<int L>
__global__ void __launch_bounds__(256, 3)
k_conv_mma(const __nv_bfloat16* __restrict__ xhi, const __nv_bfloat16* __restrict__ xlo,
           const __nv_bfloat16* __restrict__ whi, const __nv_bfloat16* __restrict__ wlo,
           const float* __restrict__ bias, float* __restrict__ out)
{
    extern __shared__ char sm[];
    const uint32_t smu = smem_u32(sm);
    const int b = blockIdx.z, l0 = blockIdx.x * 64, co0 = blockIdx.y * 128;
    const int tid = threadIdx.x, wid = tid >> 5, lane = tid & 31;
    const int wm = wid & 1, wn = wid >> 1;
    const uint32_t aHiB = smu + SM_A_HI + ((wm * 32 + (lane & 15)) * 72 + (lane >> 4) * 8) * 2;
    const uint32_t aLoB = aHiB + (SM_A_LO - SM_A_HI);
    const uint32_t bHiB = smu + SM_B_HI + ((wn * 32 + (lane & 7)) * 72 + ((lane >> 3) & 1) * 8) * 2;
    const uint32_t bLoB = bHiB + (SM_B_LO - SM_B_HI);
    float acc[2][4][4] = {};
    const int fm = tid >> 2, fq = tid & 3;
    constexpr int NCH = 24;

    for (int kc = 0; kc < NCH; kc++) {
        const int k0 = kc * 64, t = kc >> 3, ci0 = (kc & 7) * 64;
        {
            int l = l0 + fm + t - 1;
            bool ok = (unsigned)l < (unsigned)L;
            size_t so = ((size_t)b * L + (ok ? l : 0)) * NC + ci0 + fq * 16;
            uint32_t d = smu + SM_A_HI + fm * 144 + fq * 32;
            cp16(d,      xhi + so,     ok);
            cp16(d + 16, xhi + so + 8, ok);
            cp16(d + (SM_A_LO - SM_A_HI),      xlo + so,     ok);
            cp16(d + (SM_A_LO - SM_A_HI) + 16, xlo + so + 8, ok);
            #pragma unroll
            for (int j = 0; j < 4; j++) {
                int linear = tid + j * 256;
                int n = linear >> 3, c8 = linear & 7;
                size_t wo = (size_t)(co0 + n) * 1536 + k0 + c8 * 8;
                cp16(smu + SM_B_HI + n * 144 + c8 * 16, whi + wo, true);
                cp16(smu + SM_B_LO + n * 144 + c8 * 16, wlo + wo, true);
            }
        }
        CP_COMMIT();
        CP_WAIT0();
        __syncthreads();
        mma_chunk(aHiB, aLoB, bHiB, bLoB, acc);
        __syncthreads();
    }

    float* sd = reinterpret_cast<float*>(sm);
    const int g = lane >> 2, tq = lane & 3;
    #pragma unroll
    for (int i = 0; i < 2; i++) {
        int ml = wm * 32 + i * 16 + g;
        #pragma unroll
        for (int j = 0; j < 4; j++) {
            int nl = wn * 32 + j * 8 + tq * 2;
            sd[(nl)     * 68 + ml]     = acc[i][j][0];
            sd[(nl + 1) * 68 + ml]     = acc[i][j][1];
            sd[(nl)     * 68 + ml + 8] = acc[i][j][2];
            sd[(nl + 1) * 68 + ml + 8] = acc[i][j][3];
        }
    }
    __syncthreads();
    const int n = tid >> 1, half = tid & 1;
    const float bb = bias[co0 + n];
    float* op = out + ((size_t)b * NC + co0 + n) * L + l0 + half * 32;
    #pragma unroll
    for (int v = 0; v < 32; v += 4) {
        float4 d4 = *reinterpret_cast<float4*>(&sd[n * 68 + half * 32 + v]);
        float4 o;
        float v0 = d4.x + bb, v1 = d4.y + bb, v2 = d4.z + bb, v3 = d4.w + bb;
        o.x = v0 / (1.f + __expf(-v0));
        o.y = v1 / (1.f + __expf(-v1));
        o.z = v2 / (1.f + __expf(-v2));
        o.w = v3 / (1.f + __expf(-v3));
        *reinterpret_cast<float4*>(op + v) = o;
    }
}

// ---------------- plain GEMM (cp.async single buffer, 3 CTAs/SM) ----------------
// MODE 1: +PS*qfreq -> bf16 split (osh/osl). MODE 3: +bias, dup rows -> f32 out.
// MODE 4: merged k/v: n<512 -> +PS*kfreq -> bf16 split (osh/osl); n>=512 -> f32 out2.
template<int MODE, int S>
__global__ void __launch_bounds__(256, 3)
k_gemm_mma(const __nv_bfloat16* __restrict__ Ahi, const __nv_bfloat16* __restrict__ Alo,
           const __nv_bfloat16* __restrict__ whi, const __nv_bfloat16* __restrict__ wlo,
           const float* __restrict__ freqs, const float* __restrict__ bias,
           float* __restrict__ out, float* __restrict__ out2,
           __nv_bfloat16* __restrict__ osh, __nv_bfloat16* __restrict__ osl)
{
    extern __shared__ char sm[];
    const uint32_t smu = smem_u32(sm);
    const int m0 = blockIdx.y * 64, n0 = blockIdx.x * 128;
    const int tid = threadIdx.x, wid = tid >> 5, lane = tid & 31;
    const int wm = wid & 1, wn = wid >> 1;
    const uint32_t aHiB = smu + SM_A_HI + ((wm * 32 + (lane & 15)) * 72 + (lane >> 4) * 8) * 2;
    const uint32_t aLoB = aHiB + (SM_A_LO - SM_A_HI);
    const uint32_t bHiB = smu + SM_B_HI + ((wn * 32 + (lane & 7)) * 72 + ((lane >> 3) & 1) * 8) * 2;
    const uint32_t bLoB = bHiB + (SM_B_LO - SM_B_HI);
    float acc[2][4][4] = {};
    const int fm = tid >> 2, fq = tid & 3;
    constexpr int NCH = 8;

    for (int kc = 0; kc < NCH; kc++) {
        const int k0 = kc * 64;
        {
            size_t so = (size_t)(m0 + fm) * 512 + k0 + fq * 16;
            uint32_t d = smu + SM_A_HI + fm * 144 + fq * 32;
            cp16(d,      Ahi + so,     true);
            cp16(d + 16, Ahi + so + 8, true);
            cp16(d + (SM_A_LO - SM_A_HI),      Alo + so,     true);
            cp16(d + (SM_A_LO - SM_A_HI) + 16, Alo + so + 8, true);
            #pragma unroll
            for (int j = 0; j < 4; j++) {
                int linear = tid + j * 256;
                int n = linear >> 3, c8 = linear & 7;
                size_t wo = (size_t)(n0 + n) * 512 + k0 + c8 * 8;
                cp16(smu + SM_B_HI + n * 144 + c8 * 16, whi + wo, true);
                cp16(smu + SM_B_LO + n * 144 + c8 * 16, wlo + wo, true);
            }
        }
        CP_COMMIT();
        CP_WAIT0();
        __syncthreads();
        mma_chunk(aHiB, aLoB, bHiB, bLoB, acc);
        __syncthreads();
    }

    const int g = lane >> 2, tq = lane & 3;
    #pragma unroll
    for (int i = 0; i < 2; i++) {
        #pragma unroll
        for (int j = 0; j < 4; j++) {
            int ng = n0 + wn * 32 + j * 8 + tq * 2;
            #pragma unroll
            for (int r = 0; r < 2; r++) {
                int m = m0 + wm * 32 + i * 16 + g + r * 8;
                int bb_ = m / S, l = m - bb_ * S;
                float v0 = acc[i][j][r * 2], v1 = acc[i][j][r * 2 + 1];
                if (MODE == 1) {
                    const float* fp = freqs + ((size_t)bb_ * NSQ + 2 * l + 1) * NHD;
                    v0 += F_PS * fp[ng & (NHD - 1)];
                    v1 += F_PS * fp[(ng + 1) & (NHD - 1)];
                    __nv_bfloat16 h0 = __float2bfloat16(v0), h1 = __float2bfloat16(v1);
                    __nv_bfloat16 l0 = __float2bfloat16(v0 - __bfloat162float(h0));
                    __nv_bfloat16 l1 = __float2bfloat16(v1 - __bfloat162float(h1));
                    size_t off = (size_t)m * 512 + ng;
                    *reinterpret_cast<uint32_t*>(osh + off) = packhl(h0, h1);
                    *reinterpret_cast<uint32_t*>(osl + off) = packhl(l0, l1);
                } else if (MODE == 3) {
                    v0 += bias[ng];
                    v1 += bias[ng + 1];
                    float2 o = make_float2(v0, v1);
                    *reinterpret_cast<float2*>(out + ((size_t)bb_ * NSQ + 2 * l) * 512 + ng)     = o;
                    *reinterpret_cast<float2*>(out + ((size_t)bb_ * NSQ + 2 * l + 1) * 512 + ng) = o;
                } else if (MODE == 4) {
                    if (ng < 512) {
                        const float* fp = freqs + ((size_t)bb_ * S + l) * NHD;
                        v0 += F_PS * fp[ng & (NHD - 1)];
                        v1 += F_PS * fp[(ng + 1) & (NHD - 1)];
                        __nv_bfloat16 h0 = __float2bfloat16(v0), h1 = __float2bfloat16(v1);
                        __nv_bfloat16 l0 = __float2bfloat16(v0 - __bfloat162float(h0));
                        __nv_bfloat16 l1 = __float2bfloat16(v1 - __bfloat162float(h1));
                        size_t off = (size_t)m * 512 + ng;
                        *reinterpret_cast<uint32_t*>(osh + off) = packhl(h0, h1);
                        *reinterpret_cast<uint32_t*>(osl + off) = packhl(l0, l1);
                    } else {
                        *reinterpret_cast<float2*>(out2 + (size_t)m * 512 + (ng - 512)) = make_float2(v0, v1);
                    }
                }
            }
        }
    }
}

// ---------------- gaussian scores (mma, PRE-SPLIT inputs, cp.async fills) ----------------
// a0T{hi,lo}[b,h,j,i] = split(-clip(x2[i]+y2[j]-2xy, 0)/temp[h]);  M=64(j) N=128(i) K=128
__global__ void __launch_bounds__(256)
k_scores_mma(const __nv_bfloat16* __restrict__ kh, const __nv_bfloat16* __restrict__ kl,
             const __nv_bfloat16* __restrict__ qh, const __nv_bfloat16* __restrict__ ql,
             const float* __restrict__ x2, const float* __restrict__ y2,
             __nv_bfloat16* __restrict__ a0hi, __nv_bfloat16* __restrict__ a0lo)
{
    extern __shared__ char sm[];
    const uint32_t smu = smem_u32(sm);
    const int bh = blockIdx.z, b = bh >> 2, h = bh & 3;
    const int m0 = blockIdx.y * 64, n0 = blockIdx.x * 128;
    const int tid = threadIdx.x, wid = tid >> 5, lane = tid & 31;
    const int wm = wid & 1, wn = wid >> 1;
    const uint32_t aHiB = smu + SM_A_HI + ((wm * 32 + (lane & 15)) * 72 + (lane >> 4) * 8) * 2;
    const uint32_t aLoB = aHiB + (SM_A_LO - SM_A_HI);
    const uint32_t bHiB = smu + SM_B_HI + ((wn * 32 + (lane & 7)) * 72 + ((lane >> 3) & 1) * 8) * 2;
    const uint32_t bLoB = bHiB + (SM_B_LO - SM_B_HI);
    float acc[2][4][4] = {};
    const __nv_bfloat16* Abh = kh + ((size_t)b * NSKV + m0) * NC + h * NHD;
    const __nv_bfloat16* Abl = kl + ((size_t)b * NSKV + m0) * NC + h * NHD;
    const __nv_bfloat16* Bbh = qh + ((size_t)b * NSQ2 + n0) * NC + h * NHD;
    const __nv_bfloat16* Bbl = ql + ((size_t)b * NSQ2 + n0) * NC + h * NHD;

    for (int kc = 0; kc < 2; kc++) {
        const int k0 = kc * 64;
        // A fill: 64 rows x 8 c8 = 512 slots, 2/thread
        #pragma unroll
        for (int jj = 0; jj < 2; jj++) {
            int s = tid + jj * 256;
            int row = s >> 3, c8 = s & 7;
            size_t so = (size_t)row * NC + k0 + c8 * 8;
            cp16(smu + SM_A_HI + row * 144 + c8 * 16, Abh + so, true);
            cp16(smu + SM_A_LO + row * 144 + c8 * 16, Abl + so, true);
        }
        // B fill: 128 rows x 8 c8 = 1024 slots, 4/thread
        #pragma unroll
        for (int j = 0; j < 4; j++) {
            int s = tid + j * 256;
            int row = s >> 3, c8 = s & 7;
            size_t so = (size_t)row * NC + k0 + c8 * 8;
            cp16(smu + SM_B_HI + row * 144 + c8 * 16, Bbh + so, true);
            cp16(smu + SM_B_LO + row * 144 + c8 * 16, Bbl + so, true);
        }
        CP_COMMIT();
        CP_WAIT0();
        __syncthreads();
        mma_chunk(aHiB, aLoB, bHiB, bLoB, acc);
        __syncthreads();
    }

    const float invtemp = (h == 0) ? 1.f : (h == 1) ? 0.25f : (h == 2) ? (1.f / 7.f) : 0.1f;
    const int g = lane >> 2, tq = lane & 3;
    #pragma unroll
    for (int i = 0; i < 2; i++) {
        #pragma unroll
        for (int j = 0; j < 4; j++) {
            int n = n0 + wn * 32 + j * 8 + tq * 2;
            float xn0 = x2[(size_t)bh * NSQ2 + n];
            float xn1 = x2[(size_t)bh * NSQ2 + n + 1];
            #pragma unroll
            for (int r = 0; r < 2; r++) {
                int m = m0 + wm * 32 + i * 16 + g + r * 8;
                float ym = y2[(size_t)bh * NSKV + m];
                float v0 = -fmaxf(ym + xn0 - 2.f * F_S2 * acc[i][j][r * 2],     0.f) * invtemp;
                float v1 = -fmaxf(ym + xn1 - 2.f * F_S2 * acc[i][j][r * 2 + 1], 0.f) * invtemp;
                __nv_bfloat16 h0 = __float2bfloat16(v0), h1 = __float2bfloat16(v1);
                __nv_bfloat16 l0 = __float2bfloat16(v0 - __bfloat162float(h0));
                __nv_bfloat16 l1 = __float2bfloat16(v1 - __bfloat162float(h1));
                size_t off = ((size_t)bh * NSKV + m) * NSQ2 + n;
                *reinterpret_cast<uint32_t*>(a0hi + off) = packhl(h0, h1);
                *reinterpret_cast<uint32_t*>(a0lo + off) = packhl(l0, l1);
            }
        }
    }
}

// ---------------- Score Conv2d(4->4, 45x5) as Toeplitz GEMM, 512 threads, i-tile 64 ----------------
constexpr int SC_WP_BYTES    = SCW_N * 4;
constexpr int SC_TILE_STRIDE = 240;
constexpr int SC_TILE_BYTES  = 68 * SC_TILE_STRIDE;
constexpr int SC_SMEM        = SC_WP_BYTES + 8 * SC_TILE_BYTES;

__global__ void __launch_bounds__(512, 1)
k_score_conv_mma(const __nv_bfloat16* __restrict__ a0hi, const __nv_bfloat16* __restrict__ a0lo,
                 const uint32_t* __restrict__ scw, const float* __restrict__ sb,
                 const float* __restrict__ mask, float* __restrict__ attn1)
{
    extern __shared__ char sm[];
    const uint32_t smu = smem_u32(sm);
    const int b = blockIdx.z, i0 = blockIdx.y * 64, j0 = blockIdx.x * 64;
    const int tid = threadIdx.x, wid = tid >> 5, lane = tid & 31;
    const int im = (wid & 3) * 16, jn = (wid >> 2) * 16;

    uint32_t* wp = reinterpret_cast<uint32_t*>(sm);
    for (int t = tid; t < SCW_N; t += 512) wp[t] = scw[t];

    for (int t = tid; t < 4 * 68 * 14; t += 512) {
        int u  = t % 14;
        int jr = (t / 14) % 68;
        int hi = t / (14 * 68);
        int j  = j0 - 2 + jr;
        int il = i0 - 24 + u * 8;
        uint4 zh = make_uint4(0, 0, 0, 0), zl = zh;
        if ((unsigned)j < (unsigned)NSKV && (unsigned)il < (unsigned)NSQ2) {
            size_t off = ((size_t)(b * 4 + hi) * NSKV + j) * NSQ2 + il;
            zh = *reinterpret_cast<const uint4*>(a0hi + off);
            zl = *reinterpret_cast<const uint4*>(a0lo + off);
        }
        char* dh = sm + SC_WP_BYTES + (hi * 2) * SC_TILE_BYTES + jr * SC_TILE_STRIDE + u * 16;
        *reinterpret_cast<uint4*>(dh) = zh;
        *reinterpret_cast<uint4*>(dh + SC_TILE_BYTES) = zl;
    }
    __syncthreads();

    float acc[4][2][4] = {};
    const int q = lane & 3, g = lane >> 2;
    const int ip_base = 2 * q - g + 31;
    const int coff = im >> 4;
    const uint32_t lofs = (lane & 7) * SC_TILE_STRIDE + ((lane >> 3) & 1) * 16;

    for (int hi = 0; hi < 4; hi++) {
        const uint32_t tbase = smu + SC_WP_BYTES + (hi * 2) * SC_TILE_BYTES;
        #pragma unroll
        for (int s = 0; s < 5; s++) {
            const uint32_t* wpb = wp + ((hi * 5 + s) * 4) * 224;
            const uint32_t rowb = tbase + (jn + s) * SC_TILE_STRIDE + lofs + coff * 32;

            uint32_t bh[4][4], bl[4][4];
            #pragma unroll
            for (int c = 0; c < 4; c++) {
                uint32_t cb = rowb + c * 32;
                ldsm_x2(&bh[c][0], cb);
                ldsm_x2(&bh[c][2], cb + 8 * SC_TILE_STRIDE);
                ldsm_x2(&bl[c][0], cb + SC_TILE_BYTES);
                ldsm_x2(&bl[c][2], cb + SC_TILE_BYTES + 8 * SC_TILE_STRIDE);
            }

            #pragma unroll
            for (int ho = 0; ho < 4; ho++) {
                const uint32_t* wph = wpb + ho * 224;
                const uint32_t* wpl = wph + 112;
                uint32_t Wh[9], Wl[9];
                #pragma unroll
                for (int k = 0; k < 9; k++) {
                    Wh[k] = wph[ip_base - 8 + 8 * k];
                    Wl[k] = wpl[ip_base - 8 + 8 * k];
                }
                #pragma unroll
                for (int c = 0; c < 4; c++) {
                    uint32_t Ah[4] = { Wh[2*c+1], Wh[2*c], Wh[2*c+2], Wh[2*c+1] };
                    uint32_t Al[4] = { Wl[2*c+1], Wl[2*c], Wl[2*c+2], Wl[2*c+1] };
                    mma_bf16(acc[ho][0], Ah, &bh[c][0]);
                    mma_bf16(acc[ho][1], Ah, &bh[c][2]);
                    mma_bf16(acc[ho][0], Al, &bh[c][0]);
                    mma_bf16(acc[ho][1], Al, &bh[c][2]);
                    mma_bf16(acc[ho][0], Ah, &bl[c][0]);
                    mma_bf16(acc[ho][1], Ah, &bl[c][2]);
                }
            }
        }
    }

    #pragma unroll
    for (int ho = 0; ho < 4; ho++) {
        const float bb = sb[ho];
        const __nv_bfloat16* th = reinterpret_cast<const __nv_bfloat16*>(
            sm + SC_WP_BYTES + (ho * 2) * SC_TILE_BYTES);
        const __nv_bfloat16* tl = reinterpret_cast<const __nv_bfloat16*>(
            sm + SC_WP_BYTES + (ho * 2) * SC_TILE_BYTES + SC_TILE_BYTES);
        #pragma unroll
        for (int nf = 0; nf < 2; nf++) {
            int j  = j0 + jn + nf * 8 + q * 2;
            int jr = j - j0 + 2;
            #pragma unroll
            for (int r = 0; r < 2; r++) {
                int i  = i0 + im + g + r * 8;
                int ii = im + g + r * 8 + 24;
                float res0 = __bfloat162float(th[jr * 120 + ii]) + __bfloat162float(tl[jr * 120 + ii]);
                float res1 = __bfloat162float(th[(jr + 1) * 120 + ii]) + __bfloat162float(tl[(jr + 1) * 120 + ii]);
                float2 mk = *reinterpret_cast<const float2*>(mask + ((size_t)b * NSQ2 + i) * NSKV + j);
                float v0 = acc[ho][nf][r * 2]     + res0 + bb + mk.x;
                float v1 = acc[ho][nf][r * 2 + 1] + res1 + bb + mk.y;
                *reinterpret_cast<float2*>(attn1 + ((size_t)(b * 4 + ho) * NSQ2 + i) * NSKV + j) =
                    make_float2(v0, v1);
            }
        }
    }
}

// ---------------- attn @ v (cp.async single buffer, 3 CTAs/SM) ----------------
__global__ void __launch_bounds__(256, 3)
k_av_mma(const __nv_bfloat16* __restrict__ a1hi, const __nv_bfloat16* __restrict__ a1lo,
         const __nv_bfloat16* __restrict__ vthi, const __nv_bfloat16* __restrict__ vtlo,
         __nv_bfloat16* __restrict__ ybhi, __nv_bfloat16* __restrict__ yblo)
{
    extern __shared__ char sm[];
    const uint32_t smu = smem_u32(sm);
    const int bh = blockIdx.y, b = bh >> 2, h = bh & 3;
    const int m0 = blockIdx.x * 64;
    const int tid = threadIdx.x, wid = tid >> 5, lane = tid & 31;
    const int wm = wid & 1, wn = wid >> 1;
    const uint32_t aHiB = smu + SM_A_HI + ((wm * 32 + (lane & 15)) * 72 + (lane >> 4) * 8) * 2;
    const uint32_t aLoB = aHiB + (SM_A_LO - SM_A_HI);
    const uint32_t bHiB = smu + SM_B_HI + ((wn * 32 + (lane & 7)) * 72 + ((lane >> 3) & 1) * 8) * 2;
    const uint32_t bLoB = bHiB + (SM_B_LO - SM_B_HI);
    float acc[2][4][4] = {};
    const __nv_bfloat16* Ah = a1hi + ((size_t)bh * NSQ2 + m0) * NSKV;
    const __nv_bfloat16* Al = a1lo + ((size_t)bh * NSQ2 + m0) * NSKV;
    const __nv_bfloat16* Bh = vthi + ((size_t)b * NC + h * NHD) * NSKV;
    const __nv_bfloat16* Bl = vtlo + ((size_t)b * NC + h * NHD) * NSKV;
    const int fm = tid >> 2, fq = tid & 3;
    const int fn = tid >> 1, fh = tid & 1;
    constexpr int NCH = 8;

    for (int kc = 0; kc < NCH; kc++) {
        const int k0 = kc * 64;
        {
            size_t so = (size_t)fm * NSKV + k0 + fq * 16;
            uint32_t d = smu + SM_A_HI + fm * 144 + fq * 32;
            cp16(d,      Ah + so,     true);
            cp16(d + 16, Ah + so + 8, true);
            cp16(d + (SM_A_LO - SM_A_HI),      Al + so,     true);
            cp16(d + (SM_A_LO - SM_A_HI) + 16, Al + so + 8, true);
            size_t bo = (size_t)fn * NSKV + k0 + fh * 32;
            uint32_t db = smu + SM_B_HI + fn * 144 + fh * 64;
            #pragma unroll
            for (int c = 0; c < 4; c++) {
                cp16(db + c * 16, Bh + bo + c * 8, true);
                cp16(db + (SM_B_LO - SM_B_HI) + c * 16, Bl + bo + c * 8, true);
            }
        }
        CP_COMMIT();
        CP_WAIT0();
        __syncthreads();
        mma_chunk(aHiB, aLoB, bHiB, bLoB, acc);
        __syncthreads();
    }

    const int g = lane >> 2, tq = lane & 3;
    #pragma unroll
    for (int i = 0; i < 2; i++)
        #pragma unroll
        for (int j = 0; j < 4; j++) {
            int n = wn * 32 + j * 8 + tq * 2;
            #pragma unroll
            for (int r = 0; r < 2; r++) {
                int m = m0 + wm * 32 + i * 16 + g + r * 8;
                float v0 = acc[i][j][r * 2], v1 = acc[i][j][r * 2 + 1];
                __nv_bfloat16 h0 = __float2bfloat16(v0), h1 = __float2bfloat16(v1);
                __nv_bfloat16 l0 = __float2bfloat16(v0 - __bfloat162float(h0));
                __nv_bfloat16 l1 = __float2bfloat16(v1 - __bfloat162float(h1));
                size_t off = ((size_t)b * NSQ2 + m) * NC + h * NHD + n;
                *reinterpret_cast<uint32_t*>(ybhi + off) = packhl(h0, h1);
                *reinterpret_cast<uint32_t*>(yblo + off) = packhl(l0, l1);
            }
        }
}

// ---------------- elementwise / reductions ----------------
template<int L>
__global__ void k_layernorm_ch(float* __restrict__ buf, const float* __restrict__ g,
                               const float* __restrict__ bp)
{
    int col = blockIdx.x * blockDim.x + threadIdx.x;
    if (col >= NB * L) return;
    int b = col / L, l = col - b * L;
    float* p = buf + (size_t)b * NC * L + l;
    float s = 0.f, ss = 0.f;
    #pragma unroll 8
    for (int c = 0; c < NC; c++) {
        float v = p[(size_t)c * L];
        s += v; ss += v * v;
    }
    float mean = s * (1.f / NC);
    float inv  = rsqrtf(ss * (1.f / NC) - mean * mean + 1e-5f);
    #pragma unroll 8
    for (int c = 0; c < NC; c++) {
        float v = p[(size_t)c * L];
        p[(size_t)c * L] = (v - mean) * inv * g[c] + bp[c];
    }
}

template<int L>
__global__ void k_maxpool(const float* __restrict__ in, float* __restrict__ out)
{
    const int LO = L / 2;
    int idx = blockIdx.x * blockDim.x + threadIdx.x;
    if (idx >= NB * NC * LO) return;
    int lo = idx % LO;
    int bc = idx / LO;
    const float* p = in + (size_t)bc * L;
    int l = 2 * lo;
    float m = p[l];
    if (l - 1 >= 0) m = fmaxf(m, p[l - 1]);
    if (l + 1 < L)  m = fmaxf(m, p[l + 1]);
    out[idx] = m;
}

__global__ void k_transpose_cl_sp(const float* __restrict__ in,
                                  __nv_bfloat16* __restrict__ ohi,
                                  __nv_bfloat16* __restrict__ olo)
{
    __shared__ float s[32][33];
    const int b = blockIdx.z, c0 = blockIdx.y * 32, l0 = blockIdx.x * 32;
    for (int i = threadIdx.y; i < 32; i += 8)
        s[i][threadIdx.x] = in[((size_t)b * NC + c0 + i) * NSQ2 + l0 + threadIdx.x];
    __syncthreads();
    for (int i = threadIdx.y; i < 32; i += 8) {
        float v = s[threadIdx.x][i];
        __nv_bfloat16 h = __float2bfloat16(v);
        size_t off = ((size_t)b * NSQ2 + l0 + i) * NC + c0 + threadIdx.x;
        ohi[off] = h;
        olo[off] = __float2bfloat16(v - __bfloat162float(h));
    }
}

__global__ void k_transpose_v_sp(const float* __restrict__ in,
                                 __nv_bfloat16* __restrict__ ohi,
                                 __nv_bfloat16* __restrict__ olo)
{
    __shared__ float s[32][33];
    const int b = blockIdx.z, r0 = blockIdx.y * 32, c0 = blockIdx.x * 32;
    for (int i = threadIdx.y; i < 32; i += 8)
        s[i][threadIdx.x] = in[((size_t)b * 512 + r0 + i) * 512 + c0 + threadIdx.x];
    __syncthreads();
    for (int i = threadIdx.y; i < 32; i += 8) {
        float v = s[threadIdx.x][i];
        __nv_bfloat16 h = __float2bfloat16(v);
        size_t off = ((size_t)b * 512 + c0 + i) * 512 + r0 + threadIdx.x;
        ohi[off] = h;
        olo[off] = __float2bfloat16(v - __bfloat162float(h));
    }
}

__global__ void k_build_qx_sp(const float* __restrict__ x0, const float* __restrict__ x1,
                              __nv_bfloat16* __restrict__ ohi, __nv_bfloat16* __restrict__ olo)
{
    __shared__ float s[32][33];
    const int b = blockIdx.z, c0 = blockIdx.y * 32, l0 = blockIdx.x * 32;
    for (int i = threadIdx.y; i < 32; i += 8) {
        int l = l0 + threadIdx.x;
        s[i][threadIdx.x] = x0[((size_t)b * NC + c0 + i) * NSQ2 + l]
                          + x1[((size_t)b * NC + c0 + i) * NSQ4 + (l >> 1)];
    }
    __syncthreads();
    for (int i = threadIdx.y; i < 32; i += 8) {
        float v = s[threadIdx.x][i];
        __nv_bfloat16 h = __float2bfloat16(v);
        size_t off = ((size_t)b * NSQ2 + l0 + i) * NC + c0 + threadIdx.x;
        ohi[off] = h;
        olo[off] = __float2bfloat16(v - __bfloat162float(h));
    }
}

// row norms from split bf16 input
template<int S>
__global__ void k_row_norms_sp(const __nv_bfloat16* __restrict__ xh,
                               const __nv_bfloat16* __restrict__ xl, float* __restrict__ o)
{
    int gid  = blockIdx.x * (blockDim.x / 32) + (threadIdx.x >> 5);
    int lane = threadIdx.x & 31;
    if (gid >= NB * NH * S) return;
    int b = gid / (NH * S);
    int r = gid - b * NH * S;
    int h = r / S, i = r - h * S;
    size_t base = ((size_t)b * S + i) * NC + h * NHD;
    float s = 0.f;
    #pragma unroll
    for (int d = lane; d < NHD; d += 32) {
        float f = __bfloat162float(xh[base + d]) + __bfloat162float(xl[base + d]);
        s += f * f;
    }
    #pragma unroll
    for (int off = 16; off; off >>= 1) s += __shfl_xor_sync(0xffffffffu, s, off);
    if (lane == 0) o[gid] = s * F_S2;
}

__global__ void __launch_bounds__(128)
k_softmax_prior(const float* __restrict__ attn, const float* __restrict__ prior,
                __nv_bfloat16* __restrict__ a1hi, __nv_bfloat16* __restrict__ a1lo,
                float* __restrict__ oattn, int write_attn)
{
    __shared__ float red[4];
    const int row = blockIdx.x;
    const int bh = row / NSQ2;
    const int i  = row - bh * NSQ2;
    const int b  = bh >> 2;
    const float* p = attn + (size_t)row * NSKV;
    const float* pr = prior + ((size_t)b * NSQ + 2 * i + 1) * NSKV;
    const int t = threadIdx.x;

    float v[4];
    #pragma unroll
    for (int j = 0; j < 4; j++) v[j] = p[t + 128 * j];

    float mx = fmaxf(fmaxf(v[0], v[1]), fmaxf(v[2], v[3]));
    #pragma unroll
    for (int off = 16; off; off >>= 1) mx = fmaxf(mx, __shfl_xor_sync(0xffffffffu, mx, off));
    if ((t & 31) == 0) red[t >> 5] = mx;
    __syncthreads();
    mx = fmaxf(fmaxf(red[0], red[1]), fmaxf(red[2], red[3]));
    __syncthreads();

    float e[4], s = 0.f;
    #pragma unroll
    for (int j = 0; j < 4; j++) { e[j] = __expf(v[j] - mx); s += e[j]; }
    #pragma unroll
    for (int off = 16; off; off >>= 1) s += __shfl_xor_sync(0xffffffffu, s, off);
    if ((t & 31) == 0) red[t >> 5] = s;
    __syncthreads();
    s = red[0] + red[1] + red[2] + red[3];
    __syncthreads();
    float inv = 1.f / s;

    float w[4], s2 = 0.f;
    #pragma unroll
    for (int j = 0; j < 4; j++) {
        w[j] = fmaxf(e[j] * inv, 1e-8f) * fmaxf(pr[t + 128 * j], 1e-8f);
        s2 += w[j];
    }
    #pragma unroll
    for (int off = 16; off; off >>= 1) s2 += __shfl_xor_sync(0xffffffffu, s2, off);
    if ((t & 31) == 0) red[t >> 5] = s2;
    __syncthreads();
    s2 = red[0] + red[1] + red[2] + red[3];
    float i2 = 1.f / (s2 + 1e-8f);

    #pragma unroll
    for (int j = 0; j < 4; j++) {
        float o = w[j] * i2;
        __nv_bfloat16 h = __float2bfloat16(o);
        size_t po = (size_t)row * NSKV + t + 128 * j;
        a1hi[po] = h;
        a1lo[po] = __float2bfloat16(o - __bfloat162float(h));
        if (write_attn) {
            size_t o0 = ((size_t)bh * NSQ + 2 * i) * NSKV + t + 128 * j;
            oattn[o0] = o;
            oattn[o0 + NSKV] = o;
        }
    }
}

// ---------------- host launcher ----------------
extern "C" void kernel_launch(void* const* d_in, const int* in_sizes, int n_in,
                              void* d_out, int out_size)
{
    (void)in_sizes; (void)n_in;
    const float* q_x    = (const float*)d_in[0];
    const float* kv_x   = (const float*)d_in[1];
    const float* qfreq  = (const float*)d_in[2];
    const float* kfreq  = (const float*)d_in[3];
    const float* mask   = (const float*)d_in[4];
    const float* prior  = (const float*)d_in[5];
    const float* qds_cw = (const float*)d_in[6];
    const float* qds_cb = (const float*)d_in[7];
    const float* qds_g  = (const float*)d_in[8];
    const float* qds_b  = (const float*)d_in[9];
    const float* qp_cw  = (const float*)d_in[10];
    const float* qp_cb  = (const float*)d_in[11];
    const float* qp_g   = (const float*)d_in[12];
    const float* qp_b   = (const float*)d_in[13];
    const float* wq     = (const float*)d_in[14];
    const float* wk     = (const float*)d_in[15];
    const float* wv     = (const float*)d_in[16];
    const float* sw     = (const float*)d_in[17];
    const float* sb     = (const float*)d_in[18];
    const float* pw     = (const float*)d_in[19];
    const float* pb     = (const float*)d_in[20];

    float* out = (float*)d_out;
    const size_t XOUT_N = (size_t)NB * NSQ * NC;
    const size_t ATT_N  = (size_t)NB * NH * NSQ * NSKV;
    int write_attn = ((size_t)out_size >= XOUT_N + ATT_N) ? 1 : 0;
    float* out_attn = out + XOUT_N;

    void* pv;
    cudaGetSymbolAddress(&pv, g_tmp); float* tmp = (float*)pv;
    cudaGetSymbolAddress(&pv, g_x0);  float* x0  = (float*)pv;
    cudaGetSymbolAddress(&pv, g_x1);  float* x1  = (float*)pv;
    cudaGetSymbolAddress(&pv, g_qx);  float* qx  = (float*)pv;
    cudaGetSymbolAddress(&pv, g_q);   float* qb  = (float*)pv;
    cudaGetSymbolAddress(&pv, g_k);   float* kb  = (float*)pv;
    cudaGetSymbolAddress(&pv, g_v);   float* vb  = (float*)pv;
    cudaGetSymbolAddress(&pv, g_x2);  float* x2b = (float*)pv;
    cudaGetSymbolAddress(&pv, g_y2);  float* y2b = (float*)pv;
    cudaGetSymbolAddress(&pv, g_a0);  float* a0  = (float*)pv;
    cudaGetSymbolAddress(&pv, g_a1);  float* a1  = (float*)pv;
    cudaGetSymbolAddress(&pv, g_y);   float* yb  = (float*)pv;
    cudaGetSymbolAddress(&pv, g_inqh);  __nv_bfloat16* inqh  = (__nv_bfloat16*)pv;
    cudaGetSymbolAddress(&pv, g_inql);  __nv_bfloat16* inql  = (__nv_bfloat16*)pv;
    cudaGetSymbolAddress(&pv, g_inkvh); __nv_bfloat16* inkvh = (__nv_bfloat16*)pv;
    cudaGetSymbolAddress(&pv, g_inkvl); __nv_bfloat16* inkvl = (__nv_bfloat16*)pv;
    cudaGetSymbolAddress(&pv, g_whi1); __nv_bfloat16* whi1 = (__nv_bfloat16*)pv;
    cudaGetSymbolAddress(&pv, g_wlo1); __nv_bfloat16* wlo1 = (__nv_bfloat16*)pv;
    cudaGetSymbolAddress(&pv, g_whi2); __nv_bfloat16* whi2 = (__nv_bfloat16*)pv;
    cudaGetSymbolAddress(&pv, g_wlo2); __nv_bfloat16* wlo2 = (__nv_bfloat16*)pv;
    cudaGetSymbolAddress(&pv, g_pwhi); __nv_bfloat16* pwhi = (__nv_bfloat16*)pv;
    cudaGetSymbolAddress(&pv, g_pwlo); __nv_bfloat16* pwlo = (__nv_bfloat16*)pv;
    cudaGetSymbolAddress(&pv, g_scw);  uint32_t* scw = (uint32_t*)pv;

    __nv_bfloat16* a0hi = (__nv_bfloat16*)a0;
    __nv_bfloat16* a0lo = a0hi + (size_t)NB * NH * NSQ2 * NSKV;
    __nv_bfloat16* a1shi = a0hi;
    __nv_bfloat16* a1slo = a0lo;
    __nv_bfloat16* x0th = (__nv_bfloat16*)qx;
    __nv_bfloat16* x0tl = x0th + (size_t)NB * NSQ2 * NC;
    __nv_bfloat16* qxh  = x0th;
    __nv_bfloat16* qxl  = x0tl;
    __nv_bfloat16* vth  = (__nv_bfloat16*)tmp;
    __nv_bfloat16* vtl  = vth + (size_t)NB * NC * NSKV;
    __nv_bfloat16* ybh  = (__nv_bfloat16*)yb;
    __nv_bfloat16* ybl  = ybh + (size_t)NB * NSQ2 * NC;
    __nv_bfloat16* qbh  = (__nv_bfloat16*)qb;                       // q split overlay
    __nv_bfloat16* qbl  = qbh + (size_t)NB * NSQ2 * NC;
    __nv_bfloat16* kbh  = (__nv_bfloat16*)kb;                       // k split overlay
    __nv_bfloat16* kbl  = kbh + (size_t)NB * NSKV * NC;

    auto setsm = [](const void* f, int sz) {
        cudaFuncSetAttribute(f, cudaFuncAttributeMaxDynamicSharedMemorySize, sz);
        cudaFuncSetAttribute(f, cudaFuncAttributePreferredSharedMemoryCarveout, 100);
    };
    setsm((const void*)k_conv_mma<NSQ>,  SM_TOT);
    setsm((const void*)k_conv_mma<NSQ2>, SM_TOT);
    setsm((const void*)k_gemm_mma<1, NSQ2>, SM_TOT);
    setsm((const void*)k_gemm_mma<4, NSKV>, SM_TOT);
    setsm((const void*)k_gemm_mma<3, NSQ2>, SM_TOT);
    setsm((const void*)k_scores_mma, SM_TOT);
    setsm((const void*)k_av_mma, SM_TOT);
    setsm((const void*)k_score_conv_mma, SC_SMEM);

    // launch order: index 3 (ncu capture slot) = big conv
    k_prep_w<<<(NC * NC * 3 + 255) / 256, 256>>>(qds_cw, whi1, wlo1);                              // 0
    k_split<<<(NB * NSQ * NC / 4 + 255) / 256, 256>>>(q_x, inqh, inql, NB * NSQ * NC / 4);         // 1
    k_prep_w<<<(NC * NC * 3 + 255) / 256, 256>>>(qp_cw,  whi2, wlo2);                              // 2
    k_conv_mma<NSQ><<<dim3(NSQ / 64, 4, NB), 256, SM_TOT>>>(inqh, inql, whi1, wlo1, qds_cb, tmp);  // 3

    k_split<<<(NB * NSKV * NC / 4 + 255) / 256, 256>>>(kv_x, inkvh, inkvl, NB * NSKV * NC / 4);
    k_prep_plain<<<(NC * NC + 255) / 256, 256>>>(wq, pwhi, pwlo);
    k_prep_plain<<<(NC * NC + 255) / 256, 256>>>(wk, pwhi + NC * NC, pwlo + NC * NC);
    k_prep_plain<<<(NC * NC + 255) / 256, 256>>>(wv, pwhi + 2 * NC * NC, pwlo + 2 * NC * NC);
    k_prep_plain<<<(NC * NC + 255) / 256, 256>>>(pw, pwhi + 3 * NC * NC, pwlo + 3 * NC * NC);
    k_prep_scw<<<(SCW_N + 255) / 256, 256>>>(sw, scw);

    k_layernorm_ch<NSQ ><<<(NB * NSQ  + 127) / 128, 128>>>(tmp, qds_g, qds_b);
    k_maxpool<NSQ ><<<(NB * NC * NSQ2 + 255) / 256, 256>>>(tmp, x0);

    k_transpose_cl_sp<<<dim3(NSQ2 / 32, NC / 32, NB), dim3(32, 8)>>>(x0, x0th, x0tl);
    k_conv_mma<NSQ2><<<dim3(NSQ2 / 64, 4, NB), 256, SM_TOT>>>(x0th, x0tl, whi2, wlo2, qp_cb, tmp);
    k_layernorm_ch<NSQ2><<<(NB * NSQ2 + 127) / 128, 128>>>(tmp, qp_g, qp_b);
    k_maxpool<NSQ2><<<(NB * NC * NSQ4 + 255) / 256, 256>>>(tmp, x1);

    k_build_qx_sp<<<dim3(NSQ2 / 32, NC / 32, NB), dim3(32, 8)>>>(x0, x1, qxh, qxl);

    // q projection -> split bf16; merged k/v: k -> split bf16, v -> f32
    k_gemm_mma<1, NSQ2><<<dim3(4, NB * NSQ2 / 64), 256, SM_TOT>>>(qxh, qxl, pwhi, pwlo, qfreq, nullptr, nullptr, nullptr, qbh, qbl);
    k_gemm_mma<4, NSKV><<<dim3(8, NB * NSKV / 64), 256, SM_TOT>>>(inkvh, inkvl, pwhi + NC * NC, pwlo + NC * NC, kfreq, nullptr, nullptr, vb, kbh, kbl);

    k_transpose_v_sp<<<dim3(16, 16, NB), dim3(32, 8)>>>(vb, vth, vtl);

    k_row_norms_sp<NSQ2><<<NB * NH * NSQ2 / 8, 256>>>(qbh, qbl, x2b);
    k_row_norms_sp<NSKV><<<NB * NH * NSKV / 8, 256>>>(kbh, kbl, y2b);
    k_scores_mma<<<dim3(NSQ2 / 128, NSKV / 64, NB * NH), 256, SM_TOT>>>(kbh, kbl, qbh, qbl, x2b, y2b, a0hi, a0lo);

    k_score_conv_mma<<<dim3(NSKV / 64, NSQ2 / 64, NB), 512, SC_SMEM>>>(a0hi, a0lo, scw, sb, mask, a1);

    k_softmax_prior<<<NB * NH * NSQ2, 128>>>(a1, prior, a1shi, a1slo, out_attn, write_attn);

    k_av_mma<<<dim3(16, NB * NH), 256, SM_TOT>>>(a1shi, a1slo, vth, vtl, ybh, ybl);
    k_gemm_mma<3, NSQ2><<<dim3(4, NB * NSQ2 / 64), 256, SM_TOT>>>(ybh, ybl, pwhi + 3 * NC * NC, pwlo + 3 * NC * NC, nullptr, pb, out, nullptr, nullptr, nullptr);
}

// round 17
// speedup vs baseline: 1.0351x; 1.0052x over previous
#include <cuda_runtime.h>
#include <cuda_bf16.h>
#include <cstdint>
#include <cstddef>
#include <math.h>

constexpr int NB=8, NC=512, NSQ=2048, NSQ2=1024, NSQ4=512, NSKV=512, NH=4, NHD=128;
constexpr float F_PS = 0.31622776601683794f;
constexpr float F_S2 = 1.0f / 128.0f;

__device__ float g_tmp[NB * NC * NSQ];
__device__ float g_x0 [NB * NC * NSQ2];
__device__ float g_x1 [NB * NC * NSQ4];
__device__ float g_qx [NB * NSQ2 * NC];
__device__ float g_q  [NB * NSQ2 * NC];
__device__ float g_k  [NB * NSKV * NC];
__device__ float g_v  [NB * NSKV * NC];
__device__ float g_x2 [NB * NH * NSQ2];
__device__ float g_y2 [NB * NH * NSKV];
__device__ float g_a0 [NB * NH * NSQ2 * NSKV];
__device__ float g_a1 [NB * NH * NSQ2 * NSKV];
__device__ float g_y  [NB * NSQ2 * NC];
__device__ __nv_bfloat16 g_inqh [NB * NSQ * NC];
__device__ __nv_bfloat16 g_inql [NB * NSQ * NC];
__device__ __nv_bfloat16 g_inkvh[NB * NSKV * NC];
__device__ __nv_bfloat16 g_inkvl[NB * NSKV * NC];
__device__ __nv_bfloat16 g_whi1[NC * NC * 3];
__device__ __nv_bfloat16 g_wlo1[NC * NC * 3];
__device__ __nv_bfloat16 g_whi2[NC * NC * 3];
__device__ __nv_bfloat16 g_wlo2[NC * NC * 3];
__device__ __nv_bfloat16 g_pwhi[4 * NC * NC];
__device__ __nv_bfloat16 g_pwlo[4 * NC * NC];
constexpr int SCW_N = 4 * 5 * 4 * 2 * 112;
__device__ uint32_t g_scw[SCW_N];

__device__ __forceinline__ uint32_t smem_u32(const void* p) {
    uint32_t a;
    asm("{ .reg .u64 t; cvta.to.shared.u64 t, %1; cvt.u32.u64 %0, t; }" : "=r"(a) : "l"(p));
    return a;
}
__device__ __forceinline__ void ldsm_x4(uint32_t* r, uint32_t addr) {
    asm volatile("ldmatrix.sync.aligned.m8n8.x4.shared.b16 {%0,%1,%2,%3}, [%4];"
        : "=r"(r[0]), "=r"(r[1]), "=r"(r[2]), "=r"(r[3]) : "r"(addr));
}
__device__ __forceinline__ void ldsm_x2(uint32_t* r, uint32_t addr) {
    asm volatile("ldmatrix.sync.aligned.m8n8.x2.shared.b16 {%0,%1}, [%2];"
        : "=r"(r[0]), "=r"(r[1]) : "r"(addr));
}
__device__ __forceinline__ void mma_bf16(float* c, const uint32_t* a, const uint32_t* b) {
    asm volatile("mma.sync.aligned.m16n8k16.row.col.f32.bf16.bf16.f32 "
        "{%0,%1,%2,%3}, {%4,%5,%6,%7}, {%8,%9}, {%0,%1,%2,%3};"
        : "+f"(c[0]), "+f"(c[1]), "+f"(c[2]), "+f"(c[3])
        : "r"(a[0]), "r"(a[1]), "r"(a[2]), "r"(a[3]), "r"(b[0]), "r"(b[1]));
}
__device__ __forceinline__ uint32_t packhl(__nv_bfloat16 a, __nv_bfloat16 b) {
    uint16_t ua = *reinterpret_cast<uint16_t*>(&a);
    uint16_t ub = *reinterpret_cast<uint16_t*>(&b);
    return (uint32_t)ua | ((uint32_t)ub << 16);
}
__device__ __forceinline__ void split8(const float* f, uint4& hi, uint4& lo) {
    __nv_bfloat16 h[8], l[8];
    #pragma unroll
    for (int i = 0; i < 8; i++) {
        h[i] = __float2bfloat16(f[i]);
        l[i] = __float2bfloat16(f[i] - __bfloat162float(h[i]));
    }
    hi = make_uint4(packhl(h[0],h[1]), packhl(h[2],h[3]), packhl(h[4],h[5]), packhl(h[6],h[7]));
    lo = make_uint4(packhl(l[0],l[1]), packhl(l[2],l[3]), packhl(l[4],l[5]), packhl(l[6],l[7]));
}
__device__ __forceinline__ void cp16(uint32_t d, const void* s, bool ok) {
    int sz = ok ? 16 : 0;
    asm volatile("cp.async.cg.shared.global [%0], [%1], 16, %2;" :: "r"(d), "l"(s), "r"(sz) : "memory");
}
#define CP_COMMIT() asm volatile("cp.async.commit_group;" ::: "memory")
#define CP_WAIT0()  asm volatile("cp.async.wait_group 0;" ::: "memory")

constexpr int SM_A_HI = 0, SM_A_LO = 9216, SM_B_HI = 18432, SM_B_LO = 36864, SM_TOT = 55296;
// conv dual-m-tile layout: A0 hi/lo, A1 hi/lo, B hi/lo
constexpr int CV_A0 = 0, CV_A1 = 18432, CV_B_HI = 36864, CV_B_LO = 55296, CV_TOT = 73728;

__device__ __forceinline__ void mma_chunk(uint32_t aHiB, uint32_t aLoB,
                                          uint32_t bHiB, uint32_t bLoB,
                                          float acc[2][4][4]) {
    #pragma unroll
    for (int k16 = 0; k16 < 4; k16++) {
        uint32_t ah[2][4], al[2][4], bh[4][2], bl[4][2];
        #pragma unroll
        for (int i = 0; i < 2; i++) {
            ldsm_x4(ah[i], aHiB + i * 2304 + k16 * 32);
            ldsm_x4(al[i], aLoB + i * 2304 + k16 * 32);
        }
        #pragma unroll
        for (int j = 0; j < 4; j++) {
            ldsm_x2(bh[j], bHiB + j * 1152 + k16 * 32);
            ldsm_x2(bl[j], bLoB + j * 1152 + k16 * 32);
        }
        #pragma unroll
        for (int i = 0; i < 2; i++)
            #pragma unroll
            for (int j = 0; j < 4; j++) {
                mma_bf16(acc[i][j], ah[i], bh[j]);
                mma_bf16(acc[i][j], al[i], bh[j]);
                mma_bf16(acc[i][j], ah[i], bl[j]);
            }
    }
}

// ---------------- prep kernels ----------------
__global__ void k_prep_w(const float* __restrict__ w, __nv_bfloat16* __restrict__ whi,
                         __nv_bfloat16* __restrict__ wlo)
{
    int idx = blockIdx.x * blockDim.x + threadIdx.x;
    if (idx >= NC * NC * 3) return;
    int co = idx / (NC * 3);
    int kp = idx - co * (NC * 3);
    int t  = kp / NC;
    int ci = kp - t * NC;
    float f = w[(size_t)co * (NC * 3) + ci * 3 + t];
    __nv_bfloat16 h = __float2bfloat16(f);
    whi[idx] = h;
    wlo[idx] = __float2bfloat16(f - __bfloat162float(h));
}
__global__ void k_prep_plain(const float* __restrict__ w, __nv_bfloat16* __restrict__ whi,
                             __nv_bfloat16* __restrict__ wlo)
{
    int idx = blockIdx.x * blockDim.x + threadIdx.x;
    if (idx >= NC * NC) return;
    float f = w[idx];
    __nv_bfloat16 h = __float2bfloat16(f);
    whi[idx] = h;
    wlo[idx] = __float2bfloat16(f - __bfloat162float(h));
}
__global__ void k_prep_scw(const float* __restrict__ w, uint32_t* __restrict__ scw)
{
    int t = blockIdx.x * blockDim.x + threadIdx.x;
    if (t >= SCW_N) return;
    int a    = t % 112;
    int half = (t / 112) & 1;
    int ho   = (t / 224) & 3;
    int s    = (t / 896) % 5;
    int hi   = t / 4480;
    __nv_bfloat16 p[2];
    #pragma unroll
    for (int e = 0; e < 2; e++) {
        int r = a - 33 + e;
        float f = (r >= 0 && r <= 44) ? w[((size_t)(ho * 4 + hi) * 45 + r) * 5 + s] : 0.f;
        __nv_bfloat16 h = __float2bfloat16(f);
        p[e] = half ? __float2bfloat16(f - __bfloat162float(h)) : h;
    }
    scw[t] = packhl(p[0], p[1]);
}
__global__ void k_split(const float* __restrict__ in, __nv_bfloat16* __restrict__ hi,
                        __nv_bfloat16* __restrict__ lo, int n4)
{
    int i = blockIdx.x * blockDim.x + threadIdx.x;
    if (i >= n4) return;
    float4 v = reinterpret_cast<const float4*>(in)[i];
    float f[4] = { v.x, v.y, v.z, v.w };
    __nv_bfloat16 h[4], l[4];
    #pragma unroll
    for (int j = 0; j < 4; j++) {
        h[j] = __float2bfloat16(f[j]);
        l[j] = __float2bfloat16(f[j] - __bfloat162float(h[j]));
    }
    reinterpret_cast<uint2*>(hi)[i] = make_uint2(packhl(h[0], h[1]), packhl(h[2], h[3]));
    reinterpret_cast<uint2*>(lo)[i] = make_uint2(packhl(l[0], l[1]), packhl(l[2], l[3]));
}

// ---------------- conv1d k=3 (implicit GEMM, 2 l-tiles per CTA, weight reuse) ----------------
template<int L>
__global__ void __launch_bounds__(256, 2)
k_conv_mma(const __nv_bfloat16* __restrict__ xhi, const __nv_bfloat16* __restrict__ xlo,
           const __nv_bfloat16* __restrict__ whi, const __nv_bfloat16* __restrict__ wlo,
           const float* __restrict__ bias, float* __restrict__ out)
{
    extern __shared__ char sm[];
    const uint32_t smu = smem_u32(sm);
    const int b = blockIdx.z, l0 = blockIdx.x * 128, co0 = blockIdx.y * 128;
    const int tid = threadIdx.x, wid = tid >> 5, lane = tid & 31;
    const int wm = wid & 1, wn = wid >> 1;
    const uint32_t aOff = ((wm * 32 + (lane & 15)) * 72 + (lane >> 4) * 8) * 2;
    const uint32_t bHiB = smu + CV_B_HI + ((wn * 32 + (lane & 7)) * 72 + ((lane >> 3) & 1) * 8) * 2;
    const uint32_t bLoB = bHiB + (CV_B_LO - CV_B_HI);
    float acc[2][2][4][4] = {};   // [mt][i][j][frag]
    const int fm = tid >> 2, fq = tid & 3;
    constexpr int NCH = 24;

    for (int kc = 0; kc < NCH; kc++) {
        const int k0 = kc * 64, t = kc >> 3, ci0 = (kc & 7) * 64;
        #pragma unroll
        for (int mt = 0; mt < 2; mt++) {
            int l = l0 + mt * 64 + fm + t - 1;
            bool ok = (unsigned)l < (unsigned)L;
            size_t so = ((size_t)b * L + (ok ? l : 0)) * NC + ci0 + fq * 16;
            uint32_t d = smu + CV_A0 + mt * (CV_A1 - CV_A0) + fm * 144 + fq * 32;
            cp16(d,      xhi + so,     ok);
            cp16(d + 16, xhi + so + 8, ok);
            cp16(d + 9216,      xlo + so,     ok);
            cp16(d + 9216 + 16, xlo + so + 8, ok);
        }
        #pragma unroll
        for (int j = 0; j < 4; j++) {
            int linear = tid + j * 256;
            int n = linear >> 3, c8 = linear & 7;
            size_t wo = (size_t)(co0 + n) * 1536 + k0 + c8 * 8;
            cp16(smu + CV_B_HI + n * 144 + c8 * 16, whi + wo, true);
            cp16(smu + CV_B_LO + n * 144 + c8 * 16, wlo + wo, true);
        }
        CP_COMMIT();
        CP_WAIT0();
        __syncthreads();
        #pragma unroll
        for (int mt = 0; mt < 2; mt++) {
            uint32_t aHiB = smu + CV_A0 + mt * (CV_A1 - CV_A0) + aOff;
            mma_chunk(aHiB, aHiB + 9216, bHiB, bLoB, acc[mt]);
        }
        __syncthreads();
    }

    float* sd = reinterpret_cast<float*>(sm);
    const int g = lane >> 2, tq = lane & 3;
    #pragma unroll
    for (int mt = 0; mt < 2; mt++) {
        #pragma unroll
        for (int i = 0; i < 2; i++) {
            int ml = wm * 32 + i * 16 + g;
            #pragma unroll
            for (int j = 0; j < 4; j++) {
                int nl = wn * 32 + j * 8 + tq * 2;
                sd[(nl)     * 68 + ml]     = acc[mt][i][j][0];
                sd[(nl + 1) * 68 + ml]     = acc[mt][i][j][1];
                sd[(nl)     * 68 + ml + 8] = acc[mt][i][j][2];
                sd[(nl + 1) * 68 + ml + 8] = acc[mt][i][j][3];
            }
        }
        __syncthreads();
        const int n = tid >> 1, half = tid & 1;
        const float bb = bias[co0 + n];
        float* op = out + ((size_t)b * NC + co0 + n) * L + l0 + mt * 64 + half * 32;
        #pragma unroll
        for (int v = 0; v < 32; v += 4) {
            float4 d4 = *reinterpret_cast<float4*>(&sd[n * 68 + half * 32 + v]);
            float4 o;
            float v0 = d4.x + bb, v1 = d4.y + bb, v2 = d4.z + bb, v3 = d4.w + bb;
            o.x = v0 / (1.f + __expf(-v0));
            o.y = v1 / (1.f + __expf(-v1));
            o.z = v2 / (1.f + __expf(-v2));
            o.w = v3 / (1.f + __expf(-v3));
            *reinterpret_cast<float4*>(op + v) = o;
        }
        __syncthreads();
    }
}

// ---------------- plain GEMM (cp.async single buffer, 3 CTAs/SM) ----------------
// MODE 1: +PS*qfreq -> bf16 split. MODE 3: +bias, dup rows -> f32.
// MODE 4: merged k/v: n<512 -> +PS*kfreq -> bf16 split; n>=512 -> f32 out2.
template<int MODE, int S>
__global__ void __launch_bounds__(256, 3)
k_gemm_mma(const __nv_bfloat16* __restrict__ Ahi, const __nv_bfloat16* __restrict__ Alo,
           const __nv_bfloat16* __restrict__ whi, const __nv_bfloat16* __restrict__ wlo,
           const float* __restrict__ freqs, const float* __restrict__ bias,
           float* __restrict__ out, float* __restrict__ out2,
           __nv_bfloat16* __restrict__ osh, __nv_bfloat16* __restrict__ osl)
{
    extern __shared__ char sm[];
    const uint32_t smu = smem_u32(sm);
    const int m0 = blockIdx.y * 64, n0 = blockIdx.x * 128;
    const int tid = threadIdx.x, wid = tid >> 5, lane = tid & 31;
    const int wm = wid & 1, wn = wid >> 1;
    const uint32_t aHiB = smu + SM_A_HI + ((wm * 32 + (lane & 15)) * 72 + (lane >> 4) * 8) * 2;
    const uint32_t aLoB = aHiB + (SM_A_LO - SM_A_HI);
    const uint32_t bHiB = smu + SM_B_HI + ((wn * 32 + (lane & 7)) * 72 + ((lane >> 3) & 1) * 8) * 2;
    const uint32_t bLoB = bHiB + (SM_B_LO - SM_B_HI);
    float acc[2][4][4] = {};
    const int fm = tid >> 2, fq = tid & 3;
    constexpr int NCH = 8;

    for (int kc = 0; kc < NCH; kc++) {
        const int k0 = kc * 64;
        {
            size_t so = (size_t)(m0 + fm) * 512 + k0 + fq * 16;
            uint32_t d = smu + SM_A_HI + fm * 144 + fq * 32;
            cp16(d,      Ahi + so,     true);
            cp16(d + 16, Ahi + so + 8, true);
            cp16(d + (SM_A_LO - SM_A_HI),      Alo + so,     true);
            cp16(d + (SM_A_LO - SM_A_HI) + 16, Alo + so + 8, true);
            #pragma unroll
            for (int j = 0; j < 4; j++) {
                int linear = tid + j * 256;
                int n = linear >> 3, c8 = linear & 7;
                size_t wo = (size_t)(n0 + n) * 512 + k0 + c8 * 8;
                cp16(smu + SM_B_HI + n * 144 + c8 * 16, whi + wo, true);
                cp16(smu + SM_B_LO + n * 144 + c8 * 16, wlo + wo, true);
            }
        }
        CP_COMMIT();
        CP_WAIT0();
        __syncthreads();
        mma_chunk(aHiB, aLoB, bHiB, bLoB, acc);
        __syncthreads();
    }

    const int g = lane >> 2, tq = lane & 3;
    #pragma unroll
    for (int i = 0; i < 2; i++) {
        #pragma unroll
        for (int j = 0; j < 4; j++) {
            int ng = n0 + wn * 32 + j * 8 + tq * 2;
            #pragma unroll
            for (int r = 0; r < 2; r++) {
                int m = m0 + wm * 32 + i * 16 + g + r * 8;
                int bb_ = m / S, l = m - bb_ * S;
                float v0 = acc[i][j][r * 2], v1 = acc[i][j][r * 2 + 1];
                if (MODE == 1) {
                    const float* fp = freqs + ((size_t)bb_ * NSQ + 2 * l + 1) * NHD;
                    v0 += F_PS * fp[ng & (NHD - 1)];
                    v1 += F_PS * fp[(ng + 1) & (NHD - 1)];
                    __nv_bfloat16 h0 = __float2bfloat16(v0), h1 = __float2bfloat16(v1);
                    __nv_bfloat16 l0 = __float2bfloat16(v0 - __bfloat162float(h0));
                    __nv_bfloat16 l1 = __float2bfloat16(v1 - __bfloat162float(h1));
                    size_t off = (size_t)m * 512 + ng;
                    *reinterpret_cast<uint32_t*>(osh + off) = packhl(h0, h1);
                    *reinterpret_cast<uint32_t*>(osl + off) = packhl(l0, l1);
                } else if (MODE == 3) {
                    v0 += bias[ng];
                    v1 += bias[ng + 1];
                    float2 o = make_float2(v0, v1);
                    *reinterpret_cast<float2*>(out + ((size_t)bb_ * NSQ + 2 * l) * 512 + ng)     = o;
                    *reinterpret_cast<float2*>(out + ((size_t)bb_ * NSQ + 2 * l + 1) * 512 + ng) = o;
                } else if (MODE == 4) {
                    if (ng < 512) {
                        const float* fp = freqs + ((size_t)bb_ * S + l) * NHD;
                        v0 += F_PS * fp[ng & (NHD - 1)];
                        v1 += F_PS * fp[(ng + 1) & (NHD - 1)];
                        __nv_bfloat16 h0 = __float2bfloat16(v0), h1 = __float2bfloat16(v1);
                        __nv_bfloat16 l0 = __float2bfloat16(v0 - __bfloat162float(h0));
                        __nv_bfloat16 l1 = __float2bfloat16(v1 - __bfloat162float(h1));
                        size_t off = (size_t)m * 512 + ng;
                        *reinterpret_cast<uint32_t*>(osh + off) = packhl(h0, h1);
                        *reinterpret_cast<uint32_t*>(osl + off) = packhl(l0, l1);
                    } else {
                        *reinterpret_cast<float2*>(out2 + (size_t)m * 512 + (ng - 512)) = make_float2(v0, v1);
                    }
                }
            }
        }
    }
}

// ---------------- gaussian scores (mma, PRE-SPLIT inputs, cp.async fills) ----------------
__global__ void __launch_bounds__(256)
k_scores_mma(const __nv_bfloat16* __restrict__ kh, const __nv_bfloat16* __restrict__ kl,
             const __nv_bfloat16* __restrict__ qh, const __nv_bfloat16* __restrict__ ql,
             const float* __restrict__ x2, const float* __restrict__ y2,
             __nv_bfloat16* __restrict__ a0hi, __nv_bfloat16* __restrict__ a0lo)
{
    extern __shared__ char sm[];
    const uint32_t smu = smem_u32(sm);
    const int bh = blockIdx.z, b = bh >> 2, h = bh & 3;
    const int m0 = blockIdx.y * 64, n0 = blockIdx.x * 128;
    const int tid = threadIdx.x, wid = tid >> 5, lane = tid & 31;
    const int wm = wid & 1, wn = wid >> 1;
    const uint32_t aHiB = smu + SM_A_HI + ((wm * 32 + (lane & 15)) * 72 + (lane >> 4) * 8) * 2;
    const uint32_t aLoB = aHiB + (SM_A_LO - SM_A_HI);
    const uint32_t bHiB = smu + SM_B_HI + ((wn * 32 + (lane & 7)) * 72 + ((lane >> 3) & 1) * 8) * 2;
    const uint32_t bLoB = bHiB + (SM_B_LO - SM_B_HI);
    float acc[2][4][4] = {};
    const __nv_bfloat16* Abh = kh + ((size_t)b * NSKV + m0) * NC + h * NHD;
    const __nv_bfloat16* Abl = kl + ((size_t)b * NSKV + m0) * NC + h * NHD;
    const __nv_bfloat16* Bbh = qh + ((size_t)b * NSQ2 + n0) * NC + h * NHD;
    const __nv_bfloat16* Bbl = ql + ((size_t)b * NSQ2 + n0) * NC + h * NHD;

    for (int kc = 0; kc < 2; kc++) {
        const int k0 = kc * 64;
        #pragma unroll
        for (int jj = 0; jj < 2; jj++) {
            int s = tid + jj * 256;
            int row = s >> 3, c8 = s & 7;
            size_t so = (size_t)row * NC + k0 + c8 * 8;
            cp16(smu + SM_A_HI + row * 144 + c8 * 16, Abh + so, true);
            cp16(smu + SM_A_LO + row * 144 + c8 * 16, Abl + so, true);
        }
        #pragma unroll
        for (int j = 0; j < 4; j++) {
            int s = tid + j * 256;
            int row = s >> 3, c8 = s & 7;
            size_t so = (size_t)row * NC + k0 + c8 * 8;
            cp16(smu + SM_B_HI + row * 144 + c8 * 16, Bbh + so, true);
            cp16(smu + SM_B_LO + row * 144 + c8 * 16, Bbl + so, true);
        }
        CP_COMMIT();
        CP_WAIT0();
        __syncthreads();
        mma_chunk(aHiB, aLoB, bHiB, bLoB, acc);
        __syncthreads();
    }

    const float invtemp = (h == 0) ? 1.f : (h == 1) ? 0.25f : (h == 2) ? (1.f / 7.f) : 0.1f;
    const int g = lane >> 2, tq = lane & 3;
    #pragma unroll
    for (int i = 0; i < 2; i++) {
        #pragma unroll
        for (int j = 0; j < 4; j++) {
            int n = n0 + wn * 32 + j * 8 + tq * 2;
            float xn0 = x2[(size_t)bh * NSQ2 + n];
            float xn1 = x2[(size_t)bh * NSQ2 + n + 1];
            #pragma unroll
            for (int r = 0; r < 2; r++) {
                int m = m0 + wm * 32 + i * 16 + g + r * 8;
                float ym = y2[(size_t)bh * NSKV + m];
                float v0 = -fmaxf(ym + xn0 - 2.f * F_S2 * acc[i][j][r * 2],     0.f) * invtemp;
                float v1 = -fmaxf(ym + xn1 - 2.f * F_S2 * acc[i][j][r * 2 + 1], 0.f) * invtemp;
                __nv_bfloat16 h0 = __float2bfloat16(v0), h1 = __float2bfloat16(v1);
                __nv_bfloat16 l0 = __float2bfloat16(v0 - __bfloat162float(h0));
                __nv_bfloat16 l1 = __float2bfloat16(v1 - __bfloat162float(h1));
                size_t off = ((size_t)bh * NSKV + m) * NSQ2 + n;
                *reinterpret_cast<uint32_t*>(a0hi + off) = packhl(h0, h1);
                *reinterpret_cast<uint32_t*>(a0lo + off) = packhl(l0, l1);
            }
        }
    }
}

// ---------------- Score Conv2d(4->4, 45x5) as Toeplitz GEMM, 512 threads, i-tile 64 ----------------
constexpr int SC_WP_BYTES    = SCW_N * 4;
constexpr int SC_TILE_STRIDE = 240;
constexpr int SC_TILE_BYTES  = 68 * SC_TILE_STRIDE;
constexpr int SC_SMEM        = SC_WP_BYTES + 8 * SC_TILE_BYTES;

__global__ void __launch_bounds__(512, 1)
k_score_conv_mma(const __nv_bfloat16* __restrict__ a0hi, const __nv_bfloat16* __restrict__ a0lo,
                 const uint32_t* __restrict__ scw, const float* __restrict__ sb,
                 const float* __restrict__ mask, float* __restrict__ attn1)
{
    extern __shared__ char sm[];
    const uint32_t smu = smem_u32(sm);
    const int b = blockIdx.z, i0 = blockIdx.y * 64, j0 = blockIdx.x * 64;
    const int tid = threadIdx.x, wid = tid >> 5, lane = tid & 31;
    const int im = (wid & 3) * 16, jn = (wid >> 2) * 16;

    uint32_t* wp = reinterpret_cast<uint32_t*>(sm);
    for (int t = tid; t < SCW_N; t += 512) wp[t] = scw[t];

    for (int t = tid; t < 4 * 68 * 14; t += 512) {
        int u  = t % 14;
        int jr = (t / 14) % 68;
        int hi = t / (14 * 68);
        int j  = j0 - 2 + jr;
        int il = i0 - 24 + u * 8;
        uint4 zh = make_uint4(0, 0, 0, 0), zl = zh;
        if ((unsigned)j < (unsigned)NSKV && (unsigned)il < (unsigned)NSQ2) {
            size_t off = ((size_t)(b * 4 + hi) * NSKV + j) * NSQ2 + il;
            zh = *reinterpret_cast<const uint4*>(a0hi + off);
            zl = *reinterpret_cast<const uint4*>(a0lo + off);
        }
        char* dh = sm + SC_WP_BYTES + (hi * 2) * SC_TILE_BYTES + jr * SC_TILE_STRIDE + u * 16;
        *reinterpret_cast<uint4*>(dh) = zh;
        *reinterpret_cast<uint4*>(dh + SC_TILE_BYTES) = zl;
    }
    __syncthreads();

    float acc[4][2][4] = {};
    const int q = lane & 3, g = lane >> 2;
    const int ip_base = 2 * q - g + 31;
    const int coff = im >> 4;
    const uint32_t lofs = (lane & 7) * SC_TILE_STRIDE + ((lane >> 3) & 1) * 16;

    for (int hi = 0; hi < 4; hi++) {
        const uint32_t tbase = smu + SC_WP_BYTES + (hi * 2) * SC_TILE_BYTES;
        #pragma unroll
        for (int s = 0; s < 5; s++) {
            const uint32_t* wpb = wp + ((hi * 5 + s) * 4) * 224;
            const uint32_t rowb = tbase + (jn + s) * SC_TILE_STRIDE + lofs + coff * 32;

            uint32_t bh[4][4], bl[4][4];
            #pragma unroll
            for (int c = 0; c < 4; c++) {
                uint32_t cb = rowb + c * 32;
                ldsm_x2(&bh[c][0], cb);
                ldsm_x2(&bh[c][2], cb + 8 * SC_TILE_STRIDE);
                ldsm_x2(&bl[c][0], cb + SC_TILE_BYTES);
                ldsm_x2(&bl[c][2], cb + SC_TILE_BYTES + 8 * SC_TILE_STRIDE);
            }

            #pragma unroll
            for (int ho = 0; ho < 4; ho++) {
                const uint32_t* wph = wpb + ho * 224;
                const uint32_t* wpl = wph + 112;
                uint32_t Wh[9], Wl[9];
                #pragma unroll
                for (int k = 0; k < 9; k++) {
                    Wh[k] = wph[ip_base - 8 + 8 * k];
                    Wl[k] = wpl[ip_base - 8 + 8 * k];
                }
                #pragma unroll
                for (int c = 0; c < 4; c++) {
                    uint32_t Ah[4] = { Wh[2*c+1], Wh[2*c], Wh[2*c+2], Wh[2*c+1] };
                    uint32_t Al[4] = { Wl[2*c+1], Wl[2*c], Wl[2*c+2], Wl[2*c+1] };
                    mma_bf16(acc[ho][0], Ah, &bh[c][0]);
                    mma_bf16(acc[ho][1], Ah, &bh[c][2]);
                    mma_bf16(acc[ho][0], Al, &bh[c][0]);
                    mma_bf16(acc[ho][1], Al, &bh[c][2]);
                    mma_bf16(acc[ho][0], Ah, &bl[c][0]);
                    mma_bf16(acc[ho][1], Ah, &bl[c][2]);
                }
            }
        }
    }

    #pragma unroll
    for (int ho = 0; ho < 4; ho++) {
        const float bb = sb[ho];
        const __nv_bfloat16* th = reinterpret_cast<const __nv_bfloat16*>(
            sm + SC_WP_BYTES + (ho * 2) * SC_TILE_BYTES);
        const __nv_bfloat16* tl = reinterpret_cast<const __nv_bfloat16*>(
            sm + SC_WP_BYTES + (ho * 2) * SC_TILE_BYTES + SC_TILE_BYTES);
        #pragma unroll
        for (int nf = 0; nf < 2; nf++) {
            int j  = j0 + jn + nf * 8 + q * 2;
            int jr = j - j0 + 2;
            #pragma unroll
            for (int r = 0; r < 2; r++) {
                int i  = i0 + im + g + r * 8;
                int ii = im + g + r * 8 + 24;
                float res0 = __bfloat162float(th[jr * 120 + ii]) + __bfloat162float(tl[jr * 120 + ii]);
                float res1 = __bfloat162float(th[(jr + 1) * 120 + ii]) + __bfloat162float(tl[(jr + 1) * 120 + ii]);
                float2 mk = *reinterpret_cast<const float2*>(mask + ((size_t)b * NSQ2 + i) * NSKV + j);
                float v0 = acc[ho][nf][r * 2]     + res0 + bb + mk.x;
                float v1 = acc[ho][nf][r * 2 + 1] + res1 + bb + mk.y;
                *reinterpret_cast<float2*>(attn1 + ((size_t)(b * 4 + ho) * NSQ2 + i) * NSKV + j) =
                    make_float2(v0, v1);
            }
        }
    }
}

// ---------------- attn @ v (cp.async single buffer, 3 CTAs/SM) ----------------
__global__ void __launch_bounds__(256, 3)
k_av_mma(const __nv_bfloat16* __restrict__ a1hi, const __nv_bfloat16* __restrict__ a1lo,
         const __nv_bfloat16* __restrict__ vthi, const __nv_bfloat16* __restrict__ vtlo,
         __nv_bfloat16* __restrict__ ybhi, __nv_bfloat16* __restrict__ yblo)
{
    extern __shared__ char sm[];
    const uint32_t smu = smem_u32(sm);
    const int bh = blockIdx.y, b = bh >> 2, h = bh & 3;
    const int m0 = blockIdx.x * 64;
    const int tid = threadIdx.x, wid = tid >> 5, lane = tid & 31;
    const int wm = wid & 1, wn = wid >> 1;
    const uint32_t aHiB = smu + SM_A_HI + ((wm * 32 + (lane & 15)) * 72 + (lane >> 4) * 8) * 2;
    const uint32_t aLoB = aHiB + (SM_A_LO - SM_A_HI);
    const uint32_t bHiB = smu + SM_B_HI + ((wn * 32 + (lane & 7)) * 72 + ((lane >> 3) & 1) * 8) * 2;
    const uint32_t bLoB = bHiB + (SM_B_LO - SM_B_HI);
    float acc[2][4][4] = {};
    const __nv_bfloat16* Ah = a1hi + ((size_t)bh * NSQ2 + m0) * NSKV;
    const __nv_bfloat16* Al = a1lo + ((size_t)bh * NSQ2 + m0) * NSKV;
    const __nv_bfloat16* Bh = vthi + ((size_t)b * NC + h * NHD) * NSKV;
    const __nv_bfloat16* Bl = vtlo + ((size_t)b * NC + h * NHD) * NSKV;
    const int fm = tid >> 2, fq = tid & 3;
    const int fn = tid >> 1, fh = tid & 1;
    constexpr int NCH = 8;

    for (int kc = 0; kc < NCH; kc++) {
        const int k0 = kc * 64;
        {
            size_t so = (size_t)fm * NSKV + k0 + fq * 16;
            uint32_t d = smu + SM_A_HI + fm * 144 + fq * 32;
            cp16(d,      Ah + so,     true);
            cp16(d + 16, Ah + so + 8, true);
            cp16(d + (SM_A_LO - SM_A_HI),      Al + so,     true);
            cp16(d + (SM_A_LO - SM_A_HI) + 16, Al + so + 8, true);
            size_t bo = (size_t)fn * NSKV + k0 + fh * 32;
            uint32_t db = smu + SM_B_HI + fn * 144 + fh * 64;
            #pragma unroll
            for (int c = 0; c < 4; c++) {
                cp16(db + c * 16, Bh + bo + c * 8, true);
                cp16(db + (SM_B_LO - SM_B_HI) + c * 16, Bl + bo + c * 8, true);
            }
        }
        CP_COMMIT();
        CP_WAIT0();
        __syncthreads();
        mma_chunk(aHiB, aLoB, bHiB, bLoB, acc);
        __syncthreads();
    }

    const int g = lane >> 2, tq = lane & 3;
    #pragma unroll
    for (int i = 0; i < 2; i++)
        #pragma unroll
        for (int j = 0; j < 4; j++) {
            int n = wn * 32 + j * 8 + tq * 2;
            #pragma unroll
            for (int r = 0; r < 2; r++) {
                int m = m0 + wm * 32 + i * 16 + g + r * 8;
                float v0 = acc[i][j][r * 2], v1 = acc[i][j][r * 2 + 1];
                __nv_bfloat16 h0 = __float2bfloat16(v0), h1 = __float2bfloat16(v1);
                __nv_bfloat16 l0 = __float2bfloat16(v0 - __bfloat162float(h0));
                __nv_bfloat16 l1 = __float2bfloat16(v1 - __bfloat162float(h1));
                size_t off = ((size_t)b * NSQ2 + m) * NC + h * NHD + n;
                *reinterpret_cast<uint32_t*>(ybhi + off) = packhl(h0, h1);
                *reinterpret_cast<uint32_t*>(yblo + off) = packhl(l0, l1);
            }
        }
}

// ---------------- elementwise / reductions ----------------
template<int L>
__global__ void k_layernorm_ch(float* __restrict__ buf, const float* __restrict__ g,
                               const float* __restrict__ bp)
{
    int col = blockIdx.x * blockDim.x + threadIdx.x;
    if (col >= NB * L) return;
    int b = col / L, l = col - b * L;
    float* p = buf + (size_t)b * NC * L + l;
    float s = 0.f, ss = 0.f;
    #pragma unroll 8
    for (int c = 0; c < NC; c++) {
        float v = p[(size_t)c * L];
        s += v; ss += v * v;
    }
    float mean = s * (1.f / NC);
    float inv  = rsqrtf(ss * (1.f / NC) - mean * mean + 1e-5f);
    #pragma unroll 8
    for (int c = 0; c < NC; c++) {
        float v = p[(size_t)c * L];
        p[(size_t)c * L] = (v - mean) * inv * g[c] + bp[c];
    }
}

template<int L>
__global__ void k_maxpool(const float* __restrict__ in, float* __restrict__ out)
{
    const int LO = L / 2;
    int idx = blockIdx.x * blockDim.x + threadIdx.x;
    if (idx >= NB * NC * LO) return;
    int lo = idx % LO;
    int bc = idx / LO;
    const float* p = in + (size_t)bc * L;
    int l = 2 * lo;
    float m = p[l];
    if (l - 1 >= 0) m = fmaxf(m, p[l - 1]);
    if (l + 1 < L)  m = fmaxf(m, p[l + 1]);
    out[idx] = m;
}

__global__ void k_transpose_cl_sp(const float* __restrict__ in,
                                  __nv_bfloat16* __restrict__ ohi,
                                  __nv_bfloat16* __restrict__ olo)
{
    __shared__ float s[32][33];
    const int b = blockIdx.z, c0 = blockIdx.y * 32, l0 = blockIdx.x * 32;
    for (int i = threadIdx.y; i < 32; i += 8)
        s[i][threadIdx.x] = in[((size_t)b * NC + c0 + i) * NSQ2 + l0 + threadIdx.x];
    __syncthreads();
    for (int i = threadIdx.y; i < 32; i += 8) {
        float v = s[threadIdx.x][i];
        __nv_bfloat16 h = __float2bfloat16(v);
        size_t off = ((size_t)b * NSQ2 + l0 + i) * NC + c0 + threadIdx.x;
        ohi[off] = h;
        olo[off] = __float2bfloat16(v - __bfloat162float(h));
    }
}

__global__ void k_transpose_v_sp(const float* __restrict__ in,
                                 __nv_bfloat16* __restrict__ ohi,
                                 __nv_bfloat16* __restrict__ olo)
{
    __shared__ float s[32][33];
    const int b = blockIdx.z, r0 = blockIdx.y * 32, c0 = blockIdx.x * 32;
    for (int i = threadIdx.y; i < 32; i += 8)
        s[i][threadIdx.x] = in[((size_t)b * 512 + r0 + i) * 512 + c0 + threadIdx.x];
    __syncthreads();
    for (int i = threadIdx.y; i < 32; i += 8) {
        float v = s[threadIdx.x][i];
        __nv_bfloat16 h = __float2bfloat16(v);
        size_t off = ((size_t)b * 512 + c0 + i) * 512 + r0 + threadIdx.x;
        ohi[off] = h;
        olo[off] = __float2bfloat16(v - __bfloat162float(h));
    }
}

__global__ void k_build_qx_sp(const float* __restrict__ x0, const float* __restrict__ x1,
                              __nv_bfloat16* __restrict__ ohi, __nv_bfloat16* __restrict__ olo)
{
    __shared__ float s[32][33];
    const int b = blockIdx.z, c0 = blockIdx.y * 32, l0 = blockIdx.x * 32;
    for (int i = threadIdx.y; i < 32; i += 8) {
        int l = l0 + threadIdx.x;
        s[i][threadIdx.x] = x0[((size_t)b * NC + c0 + i) * NSQ2 + l]
                          + x1[((size_t)b * NC + c0 + i) * NSQ4 + (l >> 1)];
    }
    __syncthreads();
    for (int i = threadIdx.y; i < 32; i += 8) {
        float v = s[threadIdx.x][i];
        __nv_bfloat16 h = __float2bfloat16(v);
        size_t off = ((size_t)b * NSQ2 + l0 + i) * NC + c0 + threadIdx.x;
        ohi[off] = h;
        olo[off] = __float2bfloat16(v - __bfloat162float(h));
    }
}

template<int S>
__global__ void k_row_norms_sp(const __nv_bfloat16* __restrict__ xh,
                               const __nv_bfloat16* __restrict__ xl, float* __restrict__ o)
{
    int gid  = blockIdx.x * (blockDim.x / 32) + (threadIdx.x >> 5);
    int lane = threadIdx.x & 31;
    if (gid >= NB * NH * S) return;
    int b = gid / (NH * S);
    int r = gid - b * NH * S;
    int h = r / S, i = r - h * S;
    size_t base = ((size_t)b * S + i) * NC + h * NHD;
    float s = 0.f;
    #pragma unroll
    for (int d = lane; d < NHD; d += 32) {
        float f = __bfloat162float(xh[base + d]) + __bfloat162float(xl[base + d]);
        s += f * f;
    }
    #pragma unroll
    for (int off = 16; off; off >>= 1) s += __shfl_xor_sync(0xffffffffu, s, off);
    if (lane == 0) o[gid] = s * F_S2;
}

__global__ void __launch_bounds__(128)
k_softmax_prior(const float* __restrict__ attn, const float* __restrict__ prior,
                __nv_bfloat16* __restrict__ a1hi, __nv_bfloat16* __restrict__ a1lo,
                float* __restrict__ oattn, int write_attn)
{
    __shared__ float red[4];
    const int row = blockIdx.x;
    const int bh = row / NSQ2;
    const int i  = row - bh * NSQ2;
    const int b  = bh >> 2;
    const float* p = attn + (size_t)row * NSKV;
    const float* pr = prior + ((size_t)b * NSQ + 2 * i + 1) * NSKV;
    const int t = threadIdx.x;

    float v[4];
    #pragma unroll
    for (int j = 0; j < 4; j++) v[j] = p[t + 128 * j];

    float mx = fmaxf(fmaxf(v[0], v[1]), fmaxf(v[2], v[3]));
    #pragma unroll
    for (int off = 16; off; off >>= 1) mx = fmaxf(mx, __shfl_xor_sync(0xffffffffu, mx, off));
    if ((t & 31) == 0) red[t >> 5] = mx;
    __syncthreads();
    mx = fmaxf(fmaxf(red[0], red[1]), fmaxf(red[2], red[3]));
    __syncthreads();

    float e[4], s = 0.f;
    #pragma unroll
    for (int j = 0; j < 4; j++) { e[j] = __expf(v[j] - mx); s += e[j]; }
    #pragma unroll
    for (int off = 16; off; off >>= 1) s += __shfl_xor_sync(0xffffffffu, s, off);
    if ((t & 31) == 0) red[t >> 5] = s;
    __syncthreads();
    s = red[0] + red[1] + red[2] + red[3];
    __syncthreads();
    float inv = 1.f / s;

    float w[4], s2 = 0.f;
    #pragma unroll
    for (int j = 0; j < 4; j++) {
        w[j] = fmaxf(e[j] * inv, 1e-8f) * fmaxf(pr[t + 128 * j], 1e-8f);
        s2 += w[j];
    }
    #pragma unroll
    for (int off = 16; off; off >>= 1) s2 += __shfl_xor_sync(0xffffffffu, s2, off);
    if ((t & 31) == 0) red[t >> 5] = s2;
    __syncthreads();
    s2 = red[0] + red[1] + red[2] + red[3];
    float i2 = 1.f / (s2 + 1e-8f);

    #pragma unroll
    for (int j = 0; j < 4; j++) {
        float o = w[j] * i2;
        __nv_bfloat16 h = __float2bfloat16(o);
        size_t po = (size_t)row * NSKV + t + 128 * j;
        a1hi[po] = h;
        a1lo[po] = __float2bfloat16(o - __bfloat162float(h));
        if (write_attn) {
            size_t o0 = ((size_t)bh * NSQ + 2 * i) * NSKV + t + 128 * j;
            oattn[o0] = o;
            oattn[o0 + NSKV] = o;
        }
    }
}

// ---------------- host launcher ----------------
extern "C" void kernel_launch(void* const* d_in, const int* in_sizes, int n_in,
                              void* d_out, int out_size)
{
    (void)in_sizes; (void)n_in;
    const float* q_x    = (const float*)d_in[0];
    const float* kv_x   = (const float*)d_in[1];
    const float* qfreq  = (const float*)d_in[2];
    const float* kfreq  = (const float*)d_in[3];
    const float* mask   = (const float*)d_in[4];
    const float* prior  = (const float*)d_in[5];
    const float* qds_cw = (const float*)d_in[6];
    const float* qds_cb = (const float*)d_in[7];
    const float* qds_g  = (const float*)d_in[8];
    const float* qds_b  = (const float*)d_in[9];
    const float* qp_cw  = (const float*)d_in[10];
    const float* qp_cb  = (const float*)d_in[11];
    const float* qp_g   = (const float*)d_in[12];
    const float* qp_b   = (const float*)d_in[13];
    const float* wq     = (const float*)d_in[14];
    const float* wk     = (const float*)d_in[15];
    const float* wv     = (const float*)d_in[16];
    const float* sw     = (const float*)d_in[17];
    const float* sb     = (const float*)d_in[18];
    const float* pw     = (const float*)d_in[19];
    const float* pb     = (const float*)d_in[20];

    float* out = (float*)d_out;
    const size_t XOUT_N = (size_t)NB * NSQ * NC;
    const size_t ATT_N  = (size_t)NB * NH * NSQ * NSKV;
    int write_attn = ((size_t)out_size >= XOUT_N + ATT_N) ? 1 : 0;
    float* out_attn = out + XOUT_N;

    void* pv;
    cudaGetSymbolAddress(&pv, g_tmp); float* tmp = (float*)pv;
    cudaGetSymbolAddress(&pv, g_x0);  float* x0  = (float*)pv;
    cudaGetSymbolAddress(&pv, g_x1);  float* x1  = (float*)pv;
    cudaGetSymbolAddress(&pv, g_qx);  float* qx  = (float*)pv;
    cudaGetSymbolAddress(&pv, g_q);   float* qb  = (float*)pv;
    cudaGetSymbolAddress(&pv, g_k);   float* kb  = (float*)pv;
    cudaGetSymbolAddress(&pv, g_v);   float* vb  = (float*)pv;
    cudaGetSymbolAddress(&pv, g_x2);  float* x2b = (float*)pv;
    cudaGetSymbolAddress(&pv, g_y2);  float* y2b = (float*)pv;
    cudaGetSymbolAddress(&pv, g_a0);  float* a0  = (float*)pv;
    cudaGetSymbolAddress(&pv, g_a1);  float* a1  = (float*)pv;
    cudaGetSymbolAddress(&pv, g_y);   float* yb  = (float*)pv;
    cudaGetSymbolAddress(&pv, g_inqh);  __nv_bfloat16* inqh  = (__nv_bfloat16*)pv;
    cudaGetSymbolAddress(&pv, g_inql);  __nv_bfloat16* inql  = (__nv_bfloat16*)pv;
    cudaGetSymbolAddress(&pv, g_inkvh); __nv_bfloat16* inkvh = (__nv_bfloat16*)pv;
    cudaGetSymbolAddress(&pv, g_inkvl); __nv_bfloat16* inkvl = (__nv_bfloat16*)pv;
    cudaGetSymbolAddress(&pv, g_whi1); __nv_bfloat16* whi1 = (__nv_bfloat16*)pv;
    cudaGetSymbolAddress(&pv, g_wlo1); __nv_bfloat16* wlo1 = (__nv_bfloat16*)pv;
    cudaGetSymbolAddress(&pv, g_whi2); __nv_bfloat16* whi2 = (__nv_bfloat16*)pv;
    cudaGetSymbolAddress(&pv, g_wlo2); __nv_bfloat16* wlo2 = (__nv_bfloat16*)pv;
    cudaGetSymbolAddress(&pv, g_pwhi); __nv_bfloat16* pwhi = (__nv_bfloat16*)pv;
    cudaGetSymbolAddress(&pv, g_pwlo); __nv_bfloat16* pwlo = (__nv_bfloat16*)pv;
    cudaGetSymbolAddress(&pv, g_scw);  uint32_t* scw = (uint32_t*)pv;

    __nv_bfloat16* a0hi = (__nv_bfloat16*)a0;
    __nv_bfloat16* a0lo = a0hi + (size_t)NB * NH * NSQ2 * NSKV;
    __nv_bfloat16* a1shi = a0hi;
    __nv_bfloat16* a1slo = a0lo;
    __nv_bfloat16* x0th = (__nv_bfloat16*)qx;
    __nv_bfloat16* x0tl = x0th + (size_t)NB * NSQ2 * NC;
    __nv_bfloat16* qxh  = x0th;
    __nv_bfloat16* qxl  = x0tl;
    __nv_bfloat16* vth  = (__nv_bfloat16*)tmp;
    __nv_bfloat16* vtl  = vth + (size_t)NB * NC * NSKV;
    __nv_bfloat16* ybh  = (__nv_bfloat16*)yb;
    __nv_bfloat16* ybl  = ybh + (size_t)NB * NSQ2 * NC;
    __nv_bfloat16* qbh  = (__nv_bfloat16*)qb;
    __nv_bfloat16* qbl  = qbh + (size_t)NB * NSQ2 * NC;
    __nv_bfloat16* kbh  = (__nv_bfloat16*)kb;
    __nv_bfloat16* kbl  = kbh + (size_t)NB * NSKV * NC;

    auto setsm = [](const void* f, int sz) {
        cudaFuncSetAttribute(f, cudaFuncAttributeMaxDynamicSharedMemorySize, sz);
        cudaFuncSetAttribute(f, cudaFuncAttributePreferredSharedMemoryCarveout, 100);
    };
    setsm((const void*)k_conv_mma<NSQ>,  CV_TOT);
    setsm((const void*)k_conv_mma<NSQ2>, CV_TOT);
    setsm((const void*)k_gemm_mma<1, NSQ2>, SM_TOT);
    setsm((const void*)k_gemm_mma<4, NSKV>, SM_TOT);
    setsm((const void*)k_gemm_mma<3, NSQ2>, SM_TOT);
    setsm((const void*)k_scores_mma, SM_TOT);
    setsm((const void*)k_av_mma, SM_TOT);
    setsm((const void*)k_score_conv_mma, SC_SMEM);

    // launch order: index 3 (ncu capture slot) = big conv
    k_prep_w<<<(NC * NC * 3 + 255) / 256, 256>>>(qds_cw, whi1, wlo1);                              // 0
    k_split<<<(NB * NSQ * NC / 4 + 255) / 256, 256>>>(q_x, inqh, inql, NB * NSQ * NC / 4);         // 1
    k_prep_w<<<(NC * NC * 3 + 255) / 256, 256>>>(qp_cw,  whi2, wlo2);                              // 2
    k_conv_mma<NSQ><<<dim3(NSQ / 128, 4, NB), 256, CV_TOT>>>(inqh, inql, whi1, wlo1, qds_cb, tmp); // 3

    k_split<<<(NB * NSKV * NC / 4 + 255) / 256, 256>>>(kv_x, inkvh, inkvl, NB * NSKV * NC / 4);
    k_prep_plain<<<(NC * NC + 255) / 256, 256>>>(wq, pwhi, pwlo);
    k_prep_plain<<<(NC * NC + 255) / 256, 256>>>(wk, pwhi + NC * NC, pwlo + NC * NC);
    k_prep_plain<<<(NC * NC + 255) / 256, 256>>>(wv, pwhi + 2 * NC * NC, pwlo + 2 * NC * NC);
    k_prep_plain<<<(NC * NC + 255) / 256, 256>>>(pw, pwhi + 3 * NC * NC, pwlo + 3 * NC * NC);
    k_prep_scw<<<(SCW_N + 255) / 256, 256>>>(sw, scw);

    k_layernorm_ch<NSQ ><<<(NB * NSQ  + 127) / 128, 128>>>(tmp, qds_g, qds_b);
    k_maxpool<NSQ ><<<(NB * NC * NSQ2 + 255) / 256, 256>>>(tmp, x0);

    k_transpose_cl_sp<<<dim3(NSQ2 / 32, NC / 32, NB), dim3(32, 8)>>>(x0, x0th, x0tl);
    k_conv_mma<NSQ2><<<dim3(NSQ2 / 128, 4, NB), 256, CV_TOT>>>(x0th, x0tl, whi2, wlo2, qp_cb, tmp);
    k_layernorm_ch<NSQ2><<<(NB * NSQ2 + 127) / 128, 128>>>(tmp, qp_g, qp_b);
    k_maxpool<NSQ2><<<(NB * NC * NSQ4 + 255) / 256, 256>>>(tmp, x1);

    k_build_qx_sp<<<dim3(NSQ2 / 32, NC / 32, NB), dim3(32, 8)>>>(x0, x1, qxh, qxl);

    k_gemm_mma<1, NSQ2><<<dim3(4, NB * NSQ2 / 64), 256, SM_TOT>>>(qxh, qxl, pwhi, pwlo, qfreq, nullptr, nullptr, nullptr, qbh, qbl);
    k_gemm_mma<4, NSKV><<<dim3(8, NB * NSKV / 64), 256, SM_TOT>>>(inkvh, inkvl, pwhi + NC * NC, pwlo + NC * NC, kfreq, nullptr, nullptr, vb, kbh, kbl);

    k_transpose_v_sp<<<dim3(16, 16, NB), dim3(32, 8)>>>(vb, vth, vtl);

    k_row_norms_sp<NSQ2><<<NB * NH * NSQ2 / 8, 256>>>(qbh, qbl, x2b);
    k_row_norms_sp<NSKV><<<NB * NH * NSKV / 8, 256>>>(kbh, kbl, y2b);
    k_scores_mma<<<dim3(NSQ2 / 128, NSKV / 64, NB * NH), 256, SM_TOT>>>(kbh, kbl, qbh, qbl, x2b, y2b, a0hi, a0lo);

    k_score_conv_mma<<<dim3(NSKV / 64, NSQ2 / 64, NB), 512, SC_SMEM>>>(a0hi, a0lo, scw, sb, mask, a1);

    k_softmax_prior<<<NB * NH * NSQ2, 128>>>(a1, prior, a1shi, a1slo, out_attn, write_attn);

    k_av_mma<<<dim3(16, NB * NH), 256, SM_TOT>>>(a1shi, a1slo, vth, vtl, ybh, ybl);
    k_gemm_mma<3, NSQ2><<<dim3(4, NB * NSQ2 / 64), 256, SM_TOT>>>(ybh, ybl, pwhi + 3 * NC * NC, pwlo + 3 * NC * NC, nullptr, pb, out, nullptr, nullptr, nullptr);
}